// round 1
// baseline (speedup 1.0000x reference)
#include <cuda_runtime.h>
#include <math.h>

#define BATCH 4
#define MROWS 2048
#define NPTS  8192
#define NROWS (BATCH*MROWS)   // 8192
#define KNN   20
#define C0    32
#define C1    64
#define C2    256
#define NB    32              // stat-bin replicas
#define EPSB  1e-5f

// ---------------- scratch (device globals; no allocation) ----------------
__device__ float g_bins0[NB][2*C0];   // [rep][c]=sum, [rep][C0+c]=sumsq
__device__ float g_bins1[NB][2*C1];
__device__ float g_bins2[NB][2*C2];
__device__ int   g_idx[NROWS*KNN];
__device__ float g_h1[NROWS*C1];
__device__ float g_z[NROWS*C2];

__device__ __forceinline__ float gelu_exact(float x) {
    return 0.5f * x * (1.0f + erff(x * 0.70710678118654752f));
}

// ---------------- K0: zero stat bins ----------------
__global__ void k_zero() {
    int i = blockIdx.x * blockDim.x + threadIdx.x;
    if (i < NB*2*C0) (&g_bins0[0][0])[i] = 0.0f;
    if (i < NB*2*C1) (&g_bins1[0][0])[i] = 0.0f;
    if (i < NB*2*C2) (&g_bins2[0][0])[i] = 0.0f;
}

// Ordered compaction of one 256-wide chunk. All 256 threads participate.
// cnt is replicated in every thread's register (identical value).
__device__ __forceinline__ void process_chunk(float d, float r, int n, int lane, int w,
                                              int* s_wcnt, int* s_idx, int& cnt)
{
    bool p = (d <= r);
    unsigned mask = __ballot_sync(0xffffffffu, p);
    __syncthreads();                       // protect s_wcnt from previous readers
    if (lane == 0) s_wcnt[w] = __popc(mask);
    __syncthreads();
    int pre = cnt, tot = 0;
#pragma unroll
    for (int ww = 0; ww < 8; ww++) {
        int c = s_wcnt[ww];
        if (ww < w) pre += c;
        tot += c;
    }
    if (p) {
        int pos = pre + __popc(mask & ((1u << lane) - 1u));
        if (pos < KNN) s_idx[pos] = n;
    }
    cnt += tot;
}

// ---------------- K1: neighbor search + BN0 stats ----------------
__global__ __launch_bounds__(256)
void k1_scan(const float* __restrict__ centroid, const float* __restrict__ xyz,
             const float* __restrict__ radius,   const float* __restrict__ dist,
             const float* __restrict__ w_xyz,    const float* __restrict__ b_xyz)
{
    int row  = blockIdx.x;
    int t    = threadIdx.x;
    int lane = t & 31, w = t >> 5;

    __shared__ float s_wc[C0*3], s_wp[C0*3], s_b[C0];
    __shared__ int   s_idx[KNN];
    __shared__ int   s_wcnt[8];
    __shared__ float s_r1[256], s_r2[256];

    // fold weights: feat = [centroid, pf, pf-centroid]
    // h = (w0..2 - w6..8)·centroid + (w3..5 + w6..8)·pf + b
    if (t < C0) {
        float a0=w_xyz[t*9+0], a1=w_xyz[t*9+1], a2=w_xyz[t*9+2];
        float a3=w_xyz[t*9+3], a4=w_xyz[t*9+4], a5=w_xyz[t*9+5];
        float a6=w_xyz[t*9+6], a7=w_xyz[t*9+7], a8=w_xyz[t*9+8];
        s_wc[t*3+0]=a0-a6; s_wc[t*3+1]=a1-a7; s_wc[t*3+2]=a2-a8;
        s_wp[t*3+0]=a3+a6; s_wp[t*3+1]=a4+a7; s_wp[t*3+2]=a5+a8;
        s_b[t]=b_xyz[t];
    }

    float r = radius[row];
    const float* __restrict__ drow = dist + (size_t)row * NPTS;
    int cnt = 0;

    if (r < 0.015f) {
        // likely-long scan: load the full row with high MLP, then process in order
        float dv[32];
#pragma unroll
        for (int j = 0; j < 32; j++) dv[j] = drow[j*256 + t];
#pragma unroll 1
        for (int j = 0; j < 32; j++) {
            if (cnt < KNN) {    // uniform branch (cnt replicated)
                process_chunk(dv[j], r, j*256 + t, lane, w, s_wcnt, s_idx, cnt);
            }
        }
    } else {
        // early-exit scan in 512-element super-chunks (2-deep MLP)
        for (int base = 0; base < NPTS && cnt < KNN; base += 512) {
            float d0 = drow[base + t];
            float d1 = drow[base + 256 + t];
            process_chunk(d0, r, base + t,       lane, w, s_wcnt, s_idx, cnt);
            process_chunk(d1, r, base + 256 + t, lane, w, s_wcnt, s_idx, cnt);
        }
    }
    __syncthreads();

    // pad with first valid index; if none valid, JAX clamps idx=N to N-1
    if (t < KNN) {
        int first = (cnt > 0) ? s_idx[0] : (NPTS - 1);
        if (t >= cnt) s_idx[t] = first;
        g_idx[row*KNN + t] = s_idx[t];
    }
    __syncthreads();

    // h0 stats (pre-BN, per channel over all b,m,k)
    float cx = centroid[row*3+0], cy = centroid[row*3+1], cz = centroid[row*3+2];
    const float* __restrict__ xb = xyz + (size_t)(row >> 11) * NPTS * 3;
    int c = t & 31;
    float ls = 0.0f, lss = 0.0f;
#pragma unroll
    for (int i = 0; i < 3; i++) {
        int it = t + 256*i;
        if (it < KNN*C0) {
            int id = s_idx[it >> 5];
            float px = xb[id*3+0], py = xb[id*3+1], pz = xb[id*3+2];
            float h = s_b[c]
                + s_wc[c*3+0]*cx + s_wc[c*3+1]*cy + s_wc[c*3+2]*cz
                + s_wp[c*3+0]*px + s_wp[c*3+1]*py + s_wp[c*3+2]*pz;
            ls += h; lss += h*h;
        }
    }
    s_r1[t] = ls; s_r2[t] = lss;
    __syncthreads();
    if (t < C0) {
        float a = 0.0f, b2 = 0.0f;
#pragma unroll
        for (int j = 0; j < 8; j++) { a += s_r1[t + 32*j]; b2 += s_r2[t + 32*j]; }
        int rep = row & (NB - 1);
        atomicAdd(&g_bins0[rep][t], a);
        atomicAdd(&g_bins0[rep][C0 + t], b2);
    }
}

// ---------------- K2: BN0 + GELU + max_k + w1 -> h1, BN1 stats ----------------
#define K2_ROWS 16
__global__ __launch_bounds__(256)
void k2(const float* __restrict__ centroid, const float* __restrict__ xyz,
        const float* __restrict__ w_xyz,    const float* __restrict__ b_xyz,
        const float* __restrict__ g0,       const float* __restrict__ be0,
        const float* __restrict__ w1)
{
    int t = threadIdx.x;
    __shared__ float s_wc[C0*3], s_wp[C0*3], s_b[C0];
    __shared__ float s_sc0[C0], s_bi0[C0];
    __shared__ float s_w1[C1*33];        // stride 33 avoids bank conflicts
    __shared__ float s_red[256];
    __shared__ float s_x1[C0];
    __shared__ int   s_kidx[KNN];

    if (t < C0) {
        float a0=w_xyz[t*9+0], a1=w_xyz[t*9+1], a2=w_xyz[t*9+2];
        float a3=w_xyz[t*9+3], a4=w_xyz[t*9+4], a5=w_xyz[t*9+5];
        float a6=w_xyz[t*9+6], a7=w_xyz[t*9+7], a8=w_xyz[t*9+8];
        s_wc[t*3+0]=a0-a6; s_wc[t*3+1]=a1-a7; s_wc[t*3+2]=a2-a8;
        s_wp[t*3+0]=a3+a6; s_wp[t*3+1]=a4+a7; s_wp[t*3+2]=a5+a8;
        s_b[t]=b_xyz[t];
        // finalize BN0 stats (redundant per block; cheap)
        float s = 0.0f, ss = 0.0f;
        for (int rep = 0; rep < NB; rep++) { s += g_bins0[rep][t]; ss += g_bins0[rep][C0+t]; }
        float inv = 1.0f / (float)(NROWS * KNN);
        float mean = s * inv;
        float var  = ss * inv - mean * mean;
        float sc   = g0[t] * rsqrtf(var + EPSB);
        s_sc0[t] = sc; s_bi0[t] = be0[t] - mean * sc;
    }
    for (int i = t; i < C1*C0; i += 256) {
        int o = i >> 5, cc = i & 31;
        s_w1[o*33 + cc] = w1[i];
    }
    __syncthreads();

    float sum1 = 0.0f, ssq1 = 0.0f;
    for (int rr = 0; rr < K2_ROWS; rr++) {
        int row = blockIdx.x * K2_ROWS + rr;
        if (t < KNN) s_kidx[t] = g_idx[row*KNN + t];
        __syncthreads();
        float cx = centroid[row*3+0], cy = centroid[row*3+1], cz = centroid[row*3+2];
        const float* __restrict__ xb = xyz + (size_t)(row >> 11) * NPTS * 3;
        int c = t & 31;
        float lmax = -1e30f;
#pragma unroll
        for (int i = 0; i < 3; i++) {
            int it = t + 256*i;
            if (it < KNN*C0) {
                int id = s_kidx[it >> 5];
                float px = xb[id*3+0], py = xb[id*3+1], pz = xb[id*3+2];
                float h = s_b[c]
                    + s_wc[c*3+0]*cx + s_wc[c*3+1]*cy + s_wc[c*3+2]*cz
                    + s_wp[c*3+0]*px + s_wp[c*3+1]*py + s_wp[c*3+2]*pz;
                float y = gelu_exact(h * s_sc0[c] + s_bi0[c]);
                lmax = fmaxf(lmax, y);
            }
        }
        s_red[t] = lmax;
        __syncthreads();
        if (t < C0) {
            float m = s_red[t];
#pragma unroll
            for (int j = 1; j < 8; j++) m = fmaxf(m, s_red[t + 32*j]);
            s_x1[t] = m;
        }
        __syncthreads();
        if (t < C1) {
            float acc = 0.0f;
#pragma unroll
            for (int cc = 0; cc < C0; cc++) acc += s_w1[t*33 + cc] * s_x1[cc];
            g_h1[row*C1 + t] = acc;
            sum1 += acc; ssq1 += acc*acc;
        }
        __syncthreads();
    }
    if (t < C1) {
        int rep = blockIdx.x & (NB - 1);
        atomicAdd(&g_bins1[rep][t], sum1);
        atomicAdd(&g_bins1[rep][C1 + t], ssq1);
    }
}

// ---------------- K3: BN1 + GELU + w2 -> z, BN2 stats ----------------
#define K3_ROWS 16
__global__ __launch_bounds__(256)
void k3(const float* __restrict__ g1, const float* __restrict__ be1,
        const float* __restrict__ w2)
{
    int t = threadIdx.x;
    __shared__ float s_sc1[C1], s_bi1[C1];
    __shared__ float s_y[C1];

    if (t < C1) {
        float s = 0.0f, ss = 0.0f;
        for (int rep = 0; rep < NB; rep++) { s += g_bins1[rep][t]; ss += g_bins1[rep][C1+t]; }
        float inv = 1.0f / (float)NROWS;
        float mean = s * inv;
        float var  = ss * inv - mean * mean;
        float sc   = g1[t] * rsqrtf(var + EPSB);
        s_sc1[t] = sc; s_bi1[t] = be1[t] - mean * sc;
    }
    // each thread owns output channel o = t; w2 row lives in registers
    float rw[C1];
#pragma unroll
    for (int j = 0; j < C1; j++) rw[j] = w2[t*C1 + j];
    __syncthreads();

    float sum2 = 0.0f, ssq2 = 0.0f;
    for (int rr = 0; rr < K3_ROWS; rr++) {
        int row = blockIdx.x * K3_ROWS + rr;
        if (t < C1) {
            float v = g_h1[row*C1 + t];
            s_y[t] = gelu_exact(v * s_sc1[t] + s_bi1[t]);
        }
        __syncthreads();
        float a0=0.f, a1=0.f, a2=0.f, a3=0.f;
#pragma unroll
        for (int j = 0; j < C1; j += 4) {
            a0 += rw[j+0] * s_y[j+0];
            a1 += rw[j+1] * s_y[j+1];
            a2 += rw[j+2] * s_y[j+2];
            a3 += rw[j+3] * s_y[j+3];
        }
        float z = (a0 + a1) + (a2 + a3);
        g_z[row*C2 + t] = z;
        sum2 += z; ssq2 += z*z;
        __syncthreads();
    }
    int rep = blockIdx.x & (NB - 1);
    atomicAdd(&g_bins2[rep][t], sum2);
    atomicAdd(&g_bins2[rep][C2 + t], ssq2);
}

// ---------------- K4: BN2 normalize -> out ----------------
__global__ __launch_bounds__(256)
void k4(const float* __restrict__ g2, const float* __restrict__ be2,
        float* __restrict__ out)
{
    int t = threadIdx.x;
    __shared__ float s_sc[C2], s_bi[C2];
    {
        float s = 0.0f, ss = 0.0f;
        for (int rep = 0; rep < NB; rep++) { s += g_bins2[rep][t]; ss += g_bins2[rep][C2+t]; }
        float inv = 1.0f / (float)NROWS;
        float mean = s * inv;
        float var  = ss * inv - mean * mean;
        float sc   = g2[t] * rsqrtf(var + EPSB);
        s_sc[t] = sc; s_bi[t] = be2[t] - mean * sc;
    }
    __syncthreads();
    const float4* __restrict__ z4 = reinterpret_cast<const float4*>(g_z);
    float4* __restrict__ o4 = reinterpret_cast<float4*>(out);
    const int total4 = NROWS * C2 / 4;
    for (int i = blockIdx.x * 256 + t; i < total4; i += gridDim.x * 256) {
        float4 v = z4[i];
        int c = (i & 63) * 4;
        v.x = v.x * s_sc[c+0] + s_bi[c+0];
        v.y = v.y * s_sc[c+1] + s_bi[c+1];
        v.z = v.z * s_sc[c+2] + s_bi[c+2];
        v.w = v.w * s_sc[c+3] + s_bi[c+3];
        o4[i] = v;
    }
}

// ---------------- launch ----------------
extern "C" void kernel_launch(void* const* d_in, const int* in_sizes, int n_in,
                              void* d_out, int out_size)
{
    const float* centroid = (const float*)d_in[0];
    const float* xyz      = (const float*)d_in[1];
    const float* radius   = (const float*)d_in[2];
    const float* dist     = (const float*)d_in[3];
    const float* w_xyz    = (const float*)d_in[4];
    const float* b_xyz    = (const float*)d_in[5];
    const float* g0       = (const float*)d_in[6];
    const float* be0      = (const float*)d_in[7];
    const float* w1       = (const float*)d_in[8];
    const float* g1       = (const float*)d_in[9];
    const float* be1      = (const float*)d_in[10];
    const float* w2       = (const float*)d_in[11];
    const float* g2       = (const float*)d_in[12];
    const float* be2      = (const float*)d_in[13];
    float* out = (float*)d_out;

    k_zero<<<128, 256>>>();
    k1_scan<<<NROWS, 256>>>(centroid, xyz, radius, dist, w_xyz, b_xyz);
    k2<<<NROWS / K2_ROWS, 256>>>(centroid, xyz, w_xyz, b_xyz, g0, be0, w1);
    k3<<<NROWS / K3_ROWS, 256>>>(g1, be1, w2);
    k4<<<512, 256>>>(g2, be2, out);
}

// round 2
// speedup vs baseline: 1.4090x; 1.4090x over previous
#include <cuda_runtime.h>
#include <math.h>

#define BATCH 4
#define MROWS 2048
#define NPTS  8192
#define NROWS (BATCH*MROWS)   // 8192
#define KNN   20
#define C0    32
#define C1    64
#define C2    256
#define NB    32              // stat-bin replicas
#define EPSB  1e-5f

// ---------------- scratch (device globals; no allocation) ----------------
__device__ float g_bins0[NB][2*C0];
__device__ float g_bins1[NB][2*C1];
__device__ float g_bins2[NB][2*C2];
__device__ int   g_idx[NROWS*KNN];
__device__ float g_h1[NROWS*C1];
__device__ float g_yT[C1][NROWS];     // transposed gelu(bn1(h1))
__device__ float g_z[NROWS*C2];

__device__ __forceinline__ float gelu_exact(float x) {
    return 0.5f * x * (1.0f + erff(x * 0.70710678118654752f));
}

// ---------------- K0: zero stat bins ----------------
__global__ void k_zero() {
    int i = blockIdx.x * blockDim.x + threadIdx.x;
    if (i < NB*2*C0) (&g_bins0[0][0])[i] = 0.0f;
    if (i < NB*2*C1) (&g_bins1[0][0])[i] = 0.0f;
    if (i < NB*2*C2) (&g_bins2[0][0])[i] = 0.0f;
}

// Ordered compaction of one 256-wide chunk. All 256 threads participate.
__device__ __forceinline__ void process_chunk(float d, float r, int n, int lane, int w,
                                              int* s_wcnt, int* s_idx, int& cnt)
{
    bool p = (d <= r);
    unsigned mask = __ballot_sync(0xffffffffu, p);
    __syncthreads();
    if (lane == 0) s_wcnt[w] = __popc(mask);
    __syncthreads();
    int pre = cnt, tot = 0;
#pragma unroll
    for (int ww = 0; ww < 8; ww++) {
        int c = s_wcnt[ww];
        if (ww < w) pre += c;
        tot += c;
    }
    if (p) {
        int pos = pre + __popc(mask & ((1u << lane) - 1u));
        if (pos < KNN) s_idx[pos] = n;
    }
    cnt += tot;
}

// ---------------- K1: neighbor search + BN0 stats ----------------
__global__ __launch_bounds__(256)
void k1_scan(const float* __restrict__ centroid, const float* __restrict__ xyz,
             const float* __restrict__ radius,   const float* __restrict__ dist,
             const float* __restrict__ w_xyz,    const float* __restrict__ b_xyz)
{
    int row  = blockIdx.x;
    int t    = threadIdx.x;
    int lane = t & 31, w = t >> 5;

    __shared__ float s_wc[C0*3], s_wp[C0*3], s_b[C0];
    __shared__ int   s_idx[KNN];
    __shared__ int   s_wcnt[8];
    __shared__ float s_r1[256], s_r2[256];

    if (t < C0) {
        float a0=w_xyz[t*9+0], a1=w_xyz[t*9+1], a2=w_xyz[t*9+2];
        float a3=w_xyz[t*9+3], a4=w_xyz[t*9+4], a5=w_xyz[t*9+5];
        float a6=w_xyz[t*9+6], a7=w_xyz[t*9+7], a8=w_xyz[t*9+8];
        s_wc[t*3+0]=a0-a6; s_wc[t*3+1]=a1-a7; s_wc[t*3+2]=a2-a8;
        s_wp[t*3+0]=a3+a6; s_wp[t*3+1]=a4+a7; s_wp[t*3+2]=a5+a8;
        s_b[t]=b_xyz[t];
    }

    float r = radius[row];
    const float* __restrict__ drow = dist + (size_t)row * NPTS;
    int cnt = 0;

    if (r < 0.015f) {
        float dv[32];
#pragma unroll
        for (int j = 0; j < 32; j++) dv[j] = drow[j*256 + t];
#pragma unroll 1
        for (int j = 0; j < 32; j++) {
            if (cnt < KNN) {
                process_chunk(dv[j], r, j*256 + t, lane, w, s_wcnt, s_idx, cnt);
            }
        }
    } else {
        for (int base = 0; base < NPTS && cnt < KNN; base += 512) {
            float d0 = drow[base + t];
            float d1 = drow[base + 256 + t];
            process_chunk(d0, r, base + t,       lane, w, s_wcnt, s_idx, cnt);
            process_chunk(d1, r, base + 256 + t, lane, w, s_wcnt, s_idx, cnt);
        }
    }
    __syncthreads();

    if (t < KNN) {
        int first = (cnt > 0) ? s_idx[0] : (NPTS - 1);
        if (t >= cnt) s_idx[t] = first;
        g_idx[row*KNN + t] = s_idx[t];
    }
    __syncthreads();

    float cx = centroid[row*3+0], cy = centroid[row*3+1], cz = centroid[row*3+2];
    const float* __restrict__ xb = xyz + (size_t)(row >> 11) * NPTS * 3;
    int c = t & 31;
    float ls = 0.0f, lss = 0.0f;
#pragma unroll
    for (int i = 0; i < 3; i++) {
        int it = t + 256*i;
        if (it < KNN*C0) {
            int id = s_idx[it >> 5];
            float px = xb[id*3+0], py = xb[id*3+1], pz = xb[id*3+2];
            float h = s_b[c]
                + s_wc[c*3+0]*cx + s_wc[c*3+1]*cy + s_wc[c*3+2]*cz
                + s_wp[c*3+0]*px + s_wp[c*3+1]*py + s_wp[c*3+2]*pz;
            ls += h; lss += h*h;
        }
    }
    s_r1[t] = ls; s_r2[t] = lss;
    __syncthreads();
    if (t < C0) {
        float a = 0.0f, b2 = 0.0f;
#pragma unroll
        for (int j = 0; j < 8; j++) { a += s_r1[t + 32*j]; b2 += s_r2[t + 32*j]; }
        int rep = row & (NB - 1);
        atomicAdd(&g_bins0[rep][t], a);
        atomicAdd(&g_bins0[rep][C0 + t], b2);
    }
}

// ---------------- K2: BN0 + GELU + max_k + w1 -> h1, BN1 stats ----------------
#define K2_ROWS 8
__global__ __launch_bounds__(256)
void k2(const float* __restrict__ centroid, const float* __restrict__ xyz,
        const float* __restrict__ w_xyz,    const float* __restrict__ b_xyz,
        const float* __restrict__ g0,       const float* __restrict__ be0,
        const float* __restrict__ w1)
{
    int t = threadIdx.x;
    __shared__ float s_wc[C0*3], s_wp[C0*3], s_b[C0];
    __shared__ float s_sc0[C0], s_bi0[C0];
    __shared__ float s_w1[C1*33];
    __shared__ float s_red[256];
    __shared__ float s_x1[C0];
    __shared__ int   s_kidx[KNN];

    if (t < C0) {
        float a0=w_xyz[t*9+0], a1=w_xyz[t*9+1], a2=w_xyz[t*9+2];
        float a3=w_xyz[t*9+3], a4=w_xyz[t*9+4], a5=w_xyz[t*9+5];
        float a6=w_xyz[t*9+6], a7=w_xyz[t*9+7], a8=w_xyz[t*9+8];
        s_wc[t*3+0]=a0-a6; s_wc[t*3+1]=a1-a7; s_wc[t*3+2]=a2-a8;
        s_wp[t*3+0]=a3+a6; s_wp[t*3+1]=a4+a7; s_wp[t*3+2]=a5+a8;
        s_b[t]=b_xyz[t];
        float s = 0.0f, ss = 0.0f;
        for (int rep = 0; rep < NB; rep++) { s += g_bins0[rep][t]; ss += g_bins0[rep][C0+t]; }
        float inv = 1.0f / (float)(NROWS * KNN);
        float mean = s * inv;
        float var  = ss * inv - mean * mean;
        float sc   = g0[t] * rsqrtf(var + EPSB);
        s_sc0[t] = sc; s_bi0[t] = be0[t] - mean * sc;
    }
    for (int i = t; i < C1*C0; i += 256) {
        int o = i >> 5, cc = i & 31;
        s_w1[o*33 + cc] = w1[i];
    }
    __syncthreads();

    float sum1 = 0.0f, ssq1 = 0.0f;
    for (int rr = 0; rr < K2_ROWS; rr++) {
        int row = blockIdx.x * K2_ROWS + rr;
        if (t < KNN) s_kidx[t] = g_idx[row*KNN + t];
        __syncthreads();
        float cx = centroid[row*3+0], cy = centroid[row*3+1], cz = centroid[row*3+2];
        const float* __restrict__ xb = xyz + (size_t)(row >> 11) * NPTS * 3;
        int c = t & 31;
        float lmax = -1e30f;
#pragma unroll
        for (int i = 0; i < 3; i++) {
            int it = t + 256*i;
            if (it < KNN*C0) {
                int id = s_kidx[it >> 5];
                float px = xb[id*3+0], py = xb[id*3+1], pz = xb[id*3+2];
                float h = s_b[c]
                    + s_wc[c*3+0]*cx + s_wc[c*3+1]*cy + s_wc[c*3+2]*cz
                    + s_wp[c*3+0]*px + s_wp[c*3+1]*py + s_wp[c*3+2]*pz;
                float y = gelu_exact(h * s_sc0[c] + s_bi0[c]);
                lmax = fmaxf(lmax, y);
            }
        }
        s_red[t] = lmax;
        __syncthreads();
        if (t < C0) {
            float m = s_red[t];
#pragma unroll
            for (int j = 1; j < 8; j++) m = fmaxf(m, s_red[t + 32*j]);
            s_x1[t] = m;
        }
        __syncthreads();
        if (t < C1) {
            float acc = 0.0f;
#pragma unroll
            for (int cc = 0; cc < C0; cc++) acc += s_w1[t*33 + cc] * s_x1[cc];
            g_h1[row*C1 + t] = acc;
            sum1 += acc; ssq1 += acc*acc;
        }
        __syncthreads();
    }
    if (t < C1) {
        int rep = blockIdx.x & (NB - 1);
        atomicAdd(&g_bins1[rep][t], sum1);
        atomicAdd(&g_bins1[rep][C1 + t], ssq1);
    }
}

// ---------------- K3a: BN1 + GELU -> g_yT (transposed) ----------------
#define K3A_ROWS 64
__global__ __launch_bounds__(256)
void k3a(const float* __restrict__ g1, const float* __restrict__ be1)
{
    int t = threadIdx.x;
    int row0 = blockIdx.x * K3A_ROWS;
    __shared__ float s_sc[C1], s_bi[C1];
    __shared__ float s_t[C1][K3A_ROWS + 1];   // [c][r], pad to kill conflicts

    if (t < C1) {
        float s = 0.0f, ss = 0.0f;
        for (int rep = 0; rep < NB; rep++) { s += g_bins1[rep][t]; ss += g_bins1[rep][C1+t]; }
        float inv = 1.0f / (float)NROWS;
        float mean = s * inv;
        float var  = ss * inv - mean * mean;
        float sc   = g1[t] * rsqrtf(var + EPSB);
        s_sc[t] = sc; s_bi[t] = be1[t] - mean * sc;
    }
    __syncthreads();
#pragma unroll
    for (int i = 0; i < (K3A_ROWS*C1)/256; i++) {   // 16
        int j = t + i*256;
        int r = j >> 6, c = j & 63;
        float v = g_h1[(size_t)(row0 + r)*C1 + c];
        s_t[c][r] = gelu_exact(v * s_sc[c] + s_bi[c]);
    }
    __syncthreads();
#pragma unroll
    for (int i = 0; i < (K3A_ROWS*C1)/256; i++) {   // 16
        int j = t + i*256;
        int c = j >> 6, r = j & 63;
        g_yT[c][row0 + r] = s_t[c][r];
    }
}

// ---------------- K3b: z = y @ w2^T  (register-blocked, FFMA2) ----------------
#define K3B_ROWS 32
__global__ __launch_bounds__(256)
void k3b(const float* __restrict__ w2)
{
    int t = threadIdx.x;                 // output channel o = t
    int row0 = blockIdx.x * K3B_ROWS;
    __shared__ float s_yT[C1][K3B_ROWS]; // 8KB, [k][r]

    // w2 row for this output channel -> 64 registers
    float rw[C1];
    const float4* __restrict__ w4 = reinterpret_cast<const float4*>(w2 + (size_t)t * C1);
#pragma unroll
    for (int i = 0; i < C1/4; i++) {
        float4 v = w4[i];
        rw[i*4+0]=v.x; rw[i*4+1]=v.y; rw[i*4+2]=v.z; rw[i*4+3]=v.w;
    }
    // cooperative load of y tile (coalesced: 32 consecutive rows per k)
#pragma unroll
    for (int i = 0; i < (C1*K3B_ROWS)/256; i++) {   // 8
        int j = t + i*256;
        int k = j >> 5, r = j & 31;
        s_yT[k][r] = g_yT[k][row0 + r];
    }
    __syncthreads();

    unsigned long long acc[K3B_ROWS/2];
#pragma unroll
    for (int p = 0; p < K3B_ROWS/2; p++) acc[p] = 0ull;

#pragma unroll
    for (int k = 0; k < C1; k++) {
        unsigned long long ww;
        asm("mov.b64 %0, {%1, %1};" : "=l"(ww) : "f"(rw[k]));
        const unsigned long long* yp = reinterpret_cast<const unsigned long long*>(&s_yT[k][0]);
#pragma unroll
        for (int p = 0; p < K3B_ROWS/2; p++) {
            unsigned long long yy = yp[p];
            asm("fma.rn.f32x2 %0, %1, %2, %0;" : "+l"(acc[p]) : "l"(yy), "l"(ww));
        }
    }

    float sum2 = 0.0f, ssq2 = 0.0f;
#pragma unroll
    for (int p = 0; p < K3B_ROWS/2; p++) {
        float z0 = __uint_as_float((unsigned)(acc[p] & 0xffffffffull));
        float z1 = __uint_as_float((unsigned)(acc[p] >> 32));
        g_z[(size_t)(row0 + 2*p    )*C2 + t] = z0;
        g_z[(size_t)(row0 + 2*p + 1)*C2 + t] = z1;
        sum2 += z0 + z1;
        ssq2 += z0*z0 + z1*z1;
    }
    int rep = blockIdx.x & (NB - 1);
    atomicAdd(&g_bins2[rep][t], sum2);
    atomicAdd(&g_bins2[rep][C2 + t], ssq2);
}

// ---------------- K4: BN2 normalize -> out ----------------
__global__ __launch_bounds__(256)
void k4(const float* __restrict__ g2, const float* __restrict__ be2,
        float* __restrict__ out)
{
    int t = threadIdx.x;
    __shared__ float s_sc[C2], s_bi[C2];
    {
        float s = 0.0f, ss = 0.0f;
        for (int rep = 0; rep < NB; rep++) { s += g_bins2[rep][t]; ss += g_bins2[rep][C2+t]; }
        float inv = 1.0f / (float)NROWS;
        float mean = s * inv;
        float var  = ss * inv - mean * mean;
        float sc   = g2[t] * rsqrtf(var + EPSB);
        s_sc[t] = sc; s_bi[t] = be2[t] - mean * sc;
    }
    __syncthreads();
    const float4* __restrict__ z4 = reinterpret_cast<const float4*>(g_z);
    float4* __restrict__ o4 = reinterpret_cast<float4*>(out);
    const int total4 = NROWS * C2 / 4;
    for (int i = blockIdx.x * 256 + t; i < total4; i += gridDim.x * 256) {
        float4 v = z4[i];
        int c = (i & 63) * 4;
        v.x = v.x * s_sc[c+0] + s_bi[c+0];
        v.y = v.y * s_sc[c+1] + s_bi[c+1];
        v.z = v.z * s_sc[c+2] + s_bi[c+2];
        v.w = v.w * s_sc[c+3] + s_bi[c+3];
        o4[i] = v;
    }
}

// ---------------- launch ----------------
extern "C" void kernel_launch(void* const* d_in, const int* in_sizes, int n_in,
                              void* d_out, int out_size)
{
    const float* centroid = (const float*)d_in[0];
    const float* xyz      = (const float*)d_in[1];
    const float* radius   = (const float*)d_in[2];
    const float* dist     = (const float*)d_in[3];
    const float* w_xyz    = (const float*)d_in[4];
    const float* b_xyz    = (const float*)d_in[5];
    const float* g0       = (const float*)d_in[6];
    const float* be0      = (const float*)d_in[7];
    const float* w1       = (const float*)d_in[8];
    const float* g1       = (const float*)d_in[9];
    const float* be1      = (const float*)d_in[10];
    const float* w2       = (const float*)d_in[11];
    const float* g2       = (const float*)d_in[12];
    const float* be2      = (const float*)d_in[13];
    float* out = (float*)d_out;

    k_zero<<<128, 256>>>();
    k1_scan<<<NROWS, 256>>>(centroid, xyz, radius, dist, w_xyz, b_xyz);
    k2<<<NROWS / K2_ROWS, 256>>>(centroid, xyz, w_xyz, b_xyz, g0, be0, w1);
    k3a<<<NROWS / K3A_ROWS, 256>>>(g1, be1);
    k3b<<<NROWS / K3B_ROWS, 256>>>(w2);
    k4<<<512, 256>>>(g2, be2, out);
}

// round 3
// speedup vs baseline: 1.6262x; 1.1542x over previous
#include <cuda_runtime.h>
#include <math.h>

#define BATCH 4
#define MROWS 2048
#define NPTS  8192
#define NROWS (BATCH*MROWS)   // 8192
#define KNN   20
#define C0    32
#define C1    64
#define C2    256
#define NB    32              // stat-bin replicas
#define EPSB  1e-5f

// ---------------- scratch (device globals; no allocation) ----------------
__device__ float g_bins0[NB][2*C0];
__device__ float g_bins1[NB][2*C1];
__device__ float g_bins2[NB][2*C2];
__device__ int   g_idx[NROWS*KNN];
__device__ float g_h1[NROWS*C1];
__device__ float g_z[NROWS*C2];

__device__ __forceinline__ float gelu_exact(float x) {
    return 0.5f * x * (1.0f + erff(x * 0.70710678118654752f));
}

// ---------------- K0: zero stat bins ----------------
__global__ void k_zero() {
    int i = blockIdx.x * blockDim.x + threadIdx.x;
    if (i < NB*2*C0) (&g_bins0[0][0])[i] = 0.0f;
    if (i < NB*2*C1) (&g_bins1[0][0])[i] = 0.0f;
    if (i < NB*2*C2) (&g_bins2[0][0])[i] = 0.0f;
}

// Ordered compaction of one 256-wide chunk. All 256 threads participate.
__device__ __forceinline__ void process_chunk(float d, float r, int n, int lane, int w,
                                              int* s_wcnt, int* s_idx, int& cnt)
{
    bool p = (d <= r);
    unsigned mask = __ballot_sync(0xffffffffu, p);
    __syncthreads();
    if (lane == 0) s_wcnt[w] = __popc(mask);
    __syncthreads();
    int pre = cnt, tot = 0;
#pragma unroll
    for (int ww = 0; ww < 8; ww++) {
        int c = s_wcnt[ww];
        if (ww < w) pre += c;
        tot += c;
    }
    if (p) {
        int pos = pre + __popc(mask & ((1u << lane) - 1u));
        if (pos < KNN) s_idx[pos] = n;
    }
    cnt += tot;
}

// ---------------- K1: neighbor search + BN0 stats ----------------
__global__ __launch_bounds__(256)
void k1_scan(const float* __restrict__ centroid, const float* __restrict__ xyz,
             const float* __restrict__ radius,   const float* __restrict__ dist,
             const float* __restrict__ w_xyz,    const float* __restrict__ b_xyz)
{
    int row  = blockIdx.x;
    int t    = threadIdx.x;
    int lane = t & 31, w = t >> 5;

    __shared__ float s_wc[C0*3], s_wp[C0*3], s_b[C0];
    __shared__ int   s_idx[KNN];
    __shared__ int   s_wcnt[8];
    __shared__ float s_r1[256], s_r2[256];

    if (t < C0) {
        float a0=w_xyz[t*9+0], a1=w_xyz[t*9+1], a2=w_xyz[t*9+2];
        float a3=w_xyz[t*9+3], a4=w_xyz[t*9+4], a5=w_xyz[t*9+5];
        float a6=w_xyz[t*9+6], a7=w_xyz[t*9+7], a8=w_xyz[t*9+8];
        s_wc[t*3+0]=a0-a6; s_wc[t*3+1]=a1-a7; s_wc[t*3+2]=a2-a8;
        s_wp[t*3+0]=a3+a6; s_wp[t*3+1]=a4+a7; s_wp[t*3+2]=a5+a8;
        s_b[t]=b_xyz[t];
    }

    float r = radius[row];
    const float* __restrict__ drow = dist + (size_t)row * NPTS;
    int cnt = 0;

    if (r < 0.015f) {
        // long-scan path: bulk-load the whole row with max MLP, process in order
        float dv[32];
#pragma unroll
        for (int j = 0; j < 32; j++) dv[j] = drow[j*256 + t];
#pragma unroll 1
        for (int j = 0; j < 32; j++) {
            if (cnt < KNN) {
                process_chunk(dv[j], r, j*256 + t, lane, w, s_wcnt, s_idx, cnt);
            }
        }
    } else {
        // early-exit scan, software-pipelined: next chunk's loads issue before
        // processing the current chunk, hiding DRAM latency behind the barriers.
        int base = 0;
        float d0 = drow[t];
        float d1 = drow[256 + t];
        while (true) {
            int nb = base + 512;
            bool more = (nb < NPTS);
            float nd0 = 0.f, nd1 = 0.f;
            if (more) { nd0 = drow[nb + t]; nd1 = drow[nb + 256 + t]; }
            process_chunk(d0, r, base + t,       lane, w, s_wcnt, s_idx, cnt);
            process_chunk(d1, r, base + 256 + t, lane, w, s_wcnt, s_idx, cnt);
            if (cnt >= KNN || !more) break;
            base = nb; d0 = nd0; d1 = nd1;
        }
    }
    __syncthreads();

    if (t < KNN) {
        int first = (cnt > 0) ? s_idx[0] : (NPTS - 1);
        if (t >= cnt) s_idx[t] = first;
        g_idx[row*KNN + t] = s_idx[t];
    }
    __syncthreads();

    float cx = centroid[row*3+0], cy = centroid[row*3+1], cz = centroid[row*3+2];
    const float* __restrict__ xb = xyz + (size_t)(row >> 11) * NPTS * 3;
    int c = t & 31;
    float ls = 0.0f, lss = 0.0f;
#pragma unroll
    for (int i = 0; i < 3; i++) {
        int it = t + 256*i;
        if (it < KNN*C0) {
            int id = s_idx[it >> 5];
            float px = xb[id*3+0], py = xb[id*3+1], pz = xb[id*3+2];
            float h = s_b[c]
                + s_wc[c*3+0]*cx + s_wc[c*3+1]*cy + s_wc[c*3+2]*cz
                + s_wp[c*3+0]*px + s_wp[c*3+1]*py + s_wp[c*3+2]*pz;
            ls += h; lss += h*h;
        }
    }
    s_r1[t] = ls; s_r2[t] = lss;
    __syncthreads();
    if (t < C0) {
        float a = 0.0f, b2 = 0.0f;
#pragma unroll
        for (int j = 0; j < 8; j++) { a += s_r1[t + 32*j]; b2 += s_r2[t + 32*j]; }
        int rep = row & (NB - 1);
        atomicAdd(&g_bins0[rep][t], a);
        atomicAdd(&g_bins0[rep][C0 + t], b2);
    }
}

// ---------------- K2: warp-per-row BN0+GELU+max+w1 -> h1, BN1 stats ----------------
#define K2_ROWS 8          // one row per warp
__global__ __launch_bounds__(256)
void k2(const float* __restrict__ centroid, const float* __restrict__ xyz,
        const float* __restrict__ w_xyz,    const float* __restrict__ b_xyz,
        const float* __restrict__ g0,       const float* __restrict__ be0,
        const float* __restrict__ w1)
{
    int t = threadIdx.x, lane = t & 31, w = t >> 5;
    __shared__ float s_wc[C0*3], s_wp[C0*3], s_b[C0];
    __shared__ float s_sc0[C0], s_bi0[C0];
    __shared__ float s_w1[C1*33];
    __shared__ float s_sum[C1], s_ssq[C1];

    if (t < C0) {
        float a0=w_xyz[t*9+0], a1=w_xyz[t*9+1], a2=w_xyz[t*9+2];
        float a3=w_xyz[t*9+3], a4=w_xyz[t*9+4], a5=w_xyz[t*9+5];
        float a6=w_xyz[t*9+6], a7=w_xyz[t*9+7], a8=w_xyz[t*9+8];
        s_wc[t*3+0]=a0-a6; s_wc[t*3+1]=a1-a7; s_wc[t*3+2]=a2-a8;
        s_wp[t*3+0]=a3+a6; s_wp[t*3+1]=a4+a7; s_wp[t*3+2]=a5+a8;
        s_b[t]=b_xyz[t];
        float s = 0.0f, ss = 0.0f;
        for (int rep = 0; rep < NB; rep++) { s += g_bins0[rep][t]; ss += g_bins0[rep][C0+t]; }
        float inv = 1.0f / (float)(NROWS * KNN);
        float mean = s * inv;
        float var  = ss * inv - mean * mean;
        float sc   = g0[t] * rsqrtf(var + EPSB);
        s_sc0[t] = sc; s_bi0[t] = be0[t] - mean * sc;
    }
    for (int i = t; i < C1*C0; i += 256) {
        int o = i >> 5, cc = i & 31;
        s_w1[o*33 + cc] = w1[i];
    }
    if (t < C1) { s_sum[t] = 0.0f; s_ssq[t] = 0.0f; }
    __syncthreads();

    int row = blockIdx.x * K2_ROWS + w;
    float cx = centroid[row*3+0], cy = centroid[row*3+1], cz = centroid[row*3+2];
    const float* __restrict__ xb = xyz + (size_t)(row >> 11) * NPTS * 3;
    const int* __restrict__ ip = &g_idx[row*KNN];

    // lane = input channel
    float wc0=s_wc[lane*3+0], wc1=s_wc[lane*3+1], wc2=s_wc[lane*3+2];
    float wp0=s_wp[lane*3+0], wp1=s_wp[lane*3+1], wp2=s_wp[lane*3+2];
    float bb=s_b[lane], sc=s_sc0[lane], bi=s_bi0[lane];
    float base = bb + wc0*cx + wc1*cy + wc2*cz;

    float m = -1e30f;
#pragma unroll
    for (int k = 0; k < KNN; k++) {
        int id = ip[k];                 // broadcast LDG
        float px = xb[id*3+0], py = xb[id*3+1], pz = xb[id*3+2];
        float h = base + wp0*px + wp1*py + wp2*pz;
        float y = gelu_exact(h * sc + bi);
        m = fmaxf(m, y);
    }

    // 32 -> 64 matmul via warp broadcast; lane owns outputs lane and lane+32
    float acc0 = 0.0f, acc1 = 0.0f;
#pragma unroll
    for (int cc = 0; cc < C0; cc++) {
        float xv = __shfl_sync(0xffffffffu, m, cc);
        acc0 += s_w1[lane*33 + cc] * xv;
        acc1 += s_w1[(lane+32)*33 + cc] * xv;
    }
    g_h1[(size_t)row*C1 + lane]      = acc0;
    g_h1[(size_t)row*C1 + lane + 32] = acc1;

    atomicAdd(&s_sum[lane],      acc0);
    atomicAdd(&s_ssq[lane],      acc0*acc0);
    atomicAdd(&s_sum[lane+32],   acc1);
    atomicAdd(&s_ssq[lane+32],   acc1*acc1);
    __syncthreads();
    if (t < C1) {
        int rep = blockIdx.x & (NB - 1);
        atomicAdd(&g_bins1[rep][t],      s_sum[t]);
        atomicAdd(&g_bins1[rep][C1 + t], s_ssq[t]);
    }
}

// ---------------- K3: fused BN1+GELU + z = y @ w2^T (FFMA2), BN2 stats ----------------
#define K3B_ROWS 32
#define K3B_PAD  (K3B_ROWS + 2)       // keep 8B alignment of row starts
__global__ __launch_bounds__(256)
void k3b(const float* __restrict__ w2,
         const float* __restrict__ g1, const float* __restrict__ be1)
{
    int t = threadIdx.x;                 // output channel o = t
    int row0 = blockIdx.x * K3B_ROWS;
    __shared__ float s_sc[C1], s_bi[C1];
    __shared__ float s_yT[C1][K3B_PAD];

    // w2 row for this output channel -> 64 registers
    float rw[C1];
    const float4* __restrict__ w4 = reinterpret_cast<const float4*>(w2 + (size_t)t * C1);
#pragma unroll
    for (int i = 0; i < C1/4; i++) {
        float4 v = w4[i];
        rw[i*4+0]=v.x; rw[i*4+1]=v.y; rw[i*4+2]=v.z; rw[i*4+3]=v.w;
    }
    if (t < C1) {
        float s = 0.0f, ss = 0.0f;
        for (int rep = 0; rep < NB; rep++) { s += g_bins1[rep][t]; ss += g_bins1[rep][C1+t]; }
        float inv = 1.0f / (float)NROWS;
        float mean = s * inv;
        float var  = ss * inv - mean * mean;
        float sc   = g1[t] * rsqrtf(var + EPSB);
        s_sc[t] = sc; s_bi[t] = be1[t] - mean * sc;
    }
    __syncthreads();

    // load h1 tile coalesced, BN1+GELU, store transposed
#pragma unroll
    for (int i = 0; i < (K3B_ROWS*C1)/256; i++) {   // 8
        int j = t + i*256;
        int r = j >> 6, c = j & 63;
        float v = g_h1[(size_t)(row0 + r)*C1 + c];
        s_yT[c][r] = gelu_exact(v * s_sc[c] + s_bi[c]);
    }
    __syncthreads();

    unsigned long long acc[K3B_ROWS/2];
#pragma unroll
    for (int p = 0; p < K3B_ROWS/2; p++) acc[p] = 0ull;

#pragma unroll
    for (int k = 0; k < C1; k++) {
        unsigned long long ww;
        asm("mov.b64 %0, {%1, %1};" : "=l"(ww) : "f"(rw[k]));
        const unsigned long long* yp = reinterpret_cast<const unsigned long long*>(&s_yT[k][0]);
#pragma unroll
        for (int p = 0; p < K3B_ROWS/2; p++) {
            unsigned long long yy = yp[p];
            asm("fma.rn.f32x2 %0, %1, %2, %0;" : "+l"(acc[p]) : "l"(yy), "l"(ww));
        }
    }

    float sum2 = 0.0f, ssq2 = 0.0f;
#pragma unroll
    for (int p = 0; p < K3B_ROWS/2; p++) {
        float z0 = __uint_as_float((unsigned)(acc[p] & 0xffffffffull));
        float z1 = __uint_as_float((unsigned)(acc[p] >> 32));
        g_z[(size_t)(row0 + 2*p    )*C2 + t] = z0;
        g_z[(size_t)(row0 + 2*p + 1)*C2 + t] = z1;
        sum2 += z0 + z1;
        ssq2 += z0*z0 + z1*z1;
    }
    int rep = blockIdx.x & (NB - 1);
    atomicAdd(&g_bins2[rep][t], sum2);
    atomicAdd(&g_bins2[rep][C2 + t], ssq2);
}

// ---------------- K4: BN2 normalize -> out ----------------
__global__ __launch_bounds__(256)
void k4(const float* __restrict__ g2, const float* __restrict__ be2,
        float* __restrict__ out)
{
    int t = threadIdx.x;
    __shared__ float s_sc[C2], s_bi[C2];
    {
        float s = 0.0f, ss = 0.0f;
        for (int rep = 0; rep < NB; rep++) { s += g_bins2[rep][t]; ss += g_bins2[rep][C2+t]; }
        float inv = 1.0f / (float)NROWS;
        float mean = s * inv;
        float var  = ss * inv - mean * mean;
        float sc   = g2[t] * rsqrtf(var + EPSB);
        s_sc[t] = sc; s_bi[t] = be2[t] - mean * sc;
    }
    __syncthreads();
    const float4* __restrict__ z4 = reinterpret_cast<const float4*>(g_z);
    float4* __restrict__ o4 = reinterpret_cast<float4*>(out);
    const int total4 = NROWS * C2 / 4;
    for (int i = blockIdx.x * 256 + t; i < total4; i += gridDim.x * 256) {
        float4 v = z4[i];
        int c = (i & 63) * 4;
        v.x = v.x * s_sc[c+0] + s_bi[c+0];
        v.y = v.y * s_sc[c+1] + s_bi[c+1];
        v.z = v.z * s_sc[c+2] + s_bi[c+2];
        v.w = v.w * s_sc[c+3] + s_bi[c+3];
        o4[i] = v;
    }
}

// ---------------- launch ----------------
extern "C" void kernel_launch(void* const* d_in, const int* in_sizes, int n_in,
                              void* d_out, int out_size)
{
    const float* centroid = (const float*)d_in[0];
    const float* xyz      = (const float*)d_in[1];
    const float* radius   = (const float*)d_in[2];
    const float* dist     = (const float*)d_in[3];
    const float* w_xyz    = (const float*)d_in[4];
    const float* b_xyz    = (const float*)d_in[5];
    const float* g0       = (const float*)d_in[6];
    const float* be0      = (const float*)d_in[7];
    const float* w1       = (const float*)d_in[8];
    const float* g1       = (const float*)d_in[9];
    const float* be1      = (const float*)d_in[10];
    const float* w2       = (const float*)d_in[11];
    const float* g2       = (const float*)d_in[12];
    const float* be2      = (const float*)d_in[13];
    float* out = (float*)d_out;

    k_zero<<<128, 256>>>();
    k1_scan<<<NROWS, 256>>>(centroid, xyz, radius, dist, w_xyz, b_xyz);
    k2<<<NROWS / K2_ROWS, 256>>>(centroid, xyz, w_xyz, b_xyz, g0, be0, w1);
    k3b<<<NROWS / K3B_ROWS, 256>>>(w2, g1, be1);
    k4<<<512, 256>>>(g2, be2, out);
}

// round 4
// speedup vs baseline: 1.9132x; 1.1764x over previous
#include <cuda_runtime.h>
#include <math.h>

#define BATCH 4
#define MROWS 2048
#define NPTS  8192
#define NROWS (BATCH*MROWS)   // 8192
#define KNN   20
#define C0    32
#define C1    64
#define C2    256
#define NB    32              // stat-bin replicas
#define EPSB  1e-5f

// ---------------- scratch (device globals; no allocation) ----------------
__device__ float g_bins0[NB][2*C0];
__device__ float g_bins1[NB][2*C1];
__device__ float g_bins2[NB][2*C2];
__device__ int   g_idx[NROWS*KNN];
__device__ float g_h1[NROWS*C1];
__device__ float g_w2T[C1][C2];       // transposed w2: [k][o]
__device__ float g_z[NROWS*C2];

__device__ __forceinline__ float gelu_exact(float x) {
    return 0.5f * x * (1.0f + erff(x * 0.70710678118654752f));
}

// ---------------- K0: zero stat bins + transpose w2 ----------------
__global__ void k_zero(const float* __restrict__ w2) {
    int i = blockIdx.x * blockDim.x + threadIdx.x;
    if (i < NB*2*C0) (&g_bins0[0][0])[i] = 0.0f;
    if (i < NB*2*C1) (&g_bins1[0][0])[i] = 0.0f;
    if (i < NB*2*C2) (&g_bins2[0][0])[i] = 0.0f;
    if (i < C1*C2) {
        int k = i >> 8, o = i & 255;
        g_w2T[k][o] = w2[o*C1 + k];
    }
}

// Ordered compaction of one 512-element super-chunk. 2 barriers total.
__device__ __forceinline__ void process512(float d0, float d1, float r, int base, int t,
                                           int lane, int w, int* s_wcnt, int* s_idx, int& cnt)
{
    bool p0 = (d0 <= r), p1 = (d1 <= r);
    unsigned m0 = __ballot_sync(0xffffffffu, p0);
    unsigned m1 = __ballot_sync(0xffffffffu, p1);
    __syncthreads();                 // previous iteration's reads of s_wcnt done
    if (lane == 0) { s_wcnt[w] = __popc(m0); s_wcnt[8 + w] = __popc(m1); }
    __syncthreads();
    int pre0 = cnt, tot0 = 0, tot1 = 0;
#pragma unroll
    for (int ww = 0; ww < 8; ww++) { int c = s_wcnt[ww]; if (ww < w) pre0 += c; tot0 += c; }
    int pre1 = cnt + tot0;
#pragma unroll
    for (int ww = 0; ww < 8; ww++) { int c = s_wcnt[8+ww]; if (ww < w) pre1 += c; tot1 += c; }
    if (p0) {
        int pos = pre0 + __popc(m0 & ((1u << lane) - 1u));
        if (pos < KNN) s_idx[pos] = base + t;
    }
    if (p1) {
        int pos = pre1 + __popc(m1 & ((1u << lane) - 1u));
        if (pos < KNN) s_idx[pos] = base + 256 + t;
    }
    cnt += tot0 + tot1;
}

// ---------------- K1: neighbor search + BN0 stats ----------------
__global__ __launch_bounds__(256)
void k1_scan(const float* __restrict__ centroid, const float* __restrict__ xyz,
             const float* __restrict__ radius,   const float* __restrict__ dist,
             const float* __restrict__ w_xyz,    const float* __restrict__ b_xyz)
{
    int row  = blockIdx.x;
    int t    = threadIdx.x;
    int lane = t & 31, w = t >> 5;

    __shared__ float s_wc[C0*3], s_wp[C0*3], s_b[C0];
    __shared__ int   s_idx[KNN];
    __shared__ int   s_wcnt[16];
    __shared__ float s_r1[256], s_r2[256];

    if (t < C0) {
        float a0=w_xyz[t*9+0], a1=w_xyz[t*9+1], a2=w_xyz[t*9+2];
        float a3=w_xyz[t*9+3], a4=w_xyz[t*9+4], a5=w_xyz[t*9+5];
        float a6=w_xyz[t*9+6], a7=w_xyz[t*9+7], a8=w_xyz[t*9+8];
        s_wc[t*3+0]=a0-a6; s_wc[t*3+1]=a1-a7; s_wc[t*3+2]=a2-a8;
        s_wp[t*3+0]=a3+a6; s_wp[t*3+1]=a4+a7; s_wp[t*3+2]=a5+a8;
        s_b[t]=b_xyz[t];
    }

    float r = radius[row];
    const float* __restrict__ drow = dist + (size_t)row * NPTS;
    int cnt = 0;

    if (r < 0.015f) {
        // long-scan path: bulk-load the whole row with max MLP, process in order
        float dv[32];
#pragma unroll
        for (int j = 0; j < 32; j++) dv[j] = drow[j*256 + t];
#pragma unroll 1
        for (int j = 0; j < 16; j++) {
            if (cnt < KNN) {
                process512(dv[2*j], dv[2*j+1], r, j*512, t, lane, w, s_wcnt, s_idx, cnt);
            }
        }
    } else {
        // early-exit scan, software-pipelined prefetch of the next super-chunk
        int base = 0;
        float d0 = drow[t];
        float d1 = drow[256 + t];
        while (true) {
            int nb = base + 512;
            bool more = (nb < NPTS);
            float nd0 = 0.f, nd1 = 0.f;
            if (more) { nd0 = drow[nb + t]; nd1 = drow[nb + 256 + t]; }
            process512(d0, d1, r, base, t, lane, w, s_wcnt, s_idx, cnt);
            if (cnt >= KNN || !more) break;
            base = nb; d0 = nd0; d1 = nd1;
        }
    }
    __syncthreads();

    if (t < KNN) {
        int first = (cnt > 0) ? s_idx[0] : (NPTS - 1);
        if (t >= cnt) s_idx[t] = first;
        g_idx[row*KNN + t] = s_idx[t];
    }
    __syncthreads();

    float cx = centroid[row*3+0], cy = centroid[row*3+1], cz = centroid[row*3+2];
    const float* __restrict__ xb = xyz + (size_t)(row >> 11) * NPTS * 3;
    int c = t & 31;
    float ls = 0.0f, lss = 0.0f;
#pragma unroll
    for (int i = 0; i < 3; i++) {
        int it = t + 256*i;
        if (it < KNN*C0) {
            int id = s_idx[it >> 5];
            float px = xb[id*3+0], py = xb[id*3+1], pz = xb[id*3+2];
            float h = s_b[c]
                + s_wc[c*3+0]*cx + s_wc[c*3+1]*cy + s_wc[c*3+2]*cz
                + s_wp[c*3+0]*px + s_wp[c*3+1]*py + s_wp[c*3+2]*pz;
            ls += h; lss += h*h;
        }
    }
    s_r1[t] = ls; s_r2[t] = lss;
    __syncthreads();
    if (t < C0) {
        float a = 0.0f, b2 = 0.0f;
#pragma unroll
        for (int j = 0; j < 8; j++) { a += s_r1[t + 32*j]; b2 += s_r2[t + 32*j]; }
        int rep = row & (NB - 1);
        atomicAdd(&g_bins0[rep][t], a);
        atomicAdd(&g_bins0[rep][C0 + t], b2);
    }
}

// ---------------- K2: warp-per-row BN0+GELU+max+w1 -> h1, BN1 stats ----------------
#define K2_ROWS 8          // one row per warp
__global__ __launch_bounds__(256)
void k2(const float* __restrict__ centroid, const float* __restrict__ xyz,
        const float* __restrict__ w_xyz,    const float* __restrict__ b_xyz,
        const float* __restrict__ g0,       const float* __restrict__ be0,
        const float* __restrict__ w1)
{
    int t = threadIdx.x, lane = t & 31, w = t >> 5;
    __shared__ float s_wc[C0*3], s_wp[C0*3], s_b[C0];
    __shared__ float s_sc0[C0], s_bi0[C0];
    __shared__ float s_w1[C1*33];
    __shared__ float s_sum[C1], s_ssq[C1];

    if (t < C0) {
        float a0=w_xyz[t*9+0], a1=w_xyz[t*9+1], a2=w_xyz[t*9+2];
        float a3=w_xyz[t*9+3], a4=w_xyz[t*9+4], a5=w_xyz[t*9+5];
        float a6=w_xyz[t*9+6], a7=w_xyz[t*9+7], a8=w_xyz[t*9+8];
        s_wc[t*3+0]=a0-a6; s_wc[t*3+1]=a1-a7; s_wc[t*3+2]=a2-a8;
        s_wp[t*3+0]=a3+a6; s_wp[t*3+1]=a4+a7; s_wp[t*3+2]=a5+a8;
        s_b[t]=b_xyz[t];
        float s = 0.0f, ss = 0.0f;
        for (int rep = 0; rep < NB; rep++) { s += g_bins0[rep][t]; ss += g_bins0[rep][C0+t]; }
        float inv = 1.0f / (float)(NROWS * KNN);
        float mean = s * inv;
        float var  = ss * inv - mean * mean;
        float sc   = g0[t] * rsqrtf(var + EPSB);
        s_sc0[t] = sc; s_bi0[t] = be0[t] - mean * sc;
    }
    for (int i = t; i < C1*C0; i += 256) {
        int o = i >> 5, cc = i & 31;
        s_w1[o*33 + cc] = w1[i];
    }
    if (t < C1) { s_sum[t] = 0.0f; s_ssq[t] = 0.0f; }
    __syncthreads();

    int row = blockIdx.x * K2_ROWS + w;
    float cx = centroid[row*3+0], cy = centroid[row*3+1], cz = centroid[row*3+2];
    const float* __restrict__ xb = xyz + (size_t)(row >> 11) * NPTS * 3;
    const int* __restrict__ ip = &g_idx[row*KNN];

    float wc0=s_wc[lane*3+0], wc1=s_wc[lane*3+1], wc2=s_wc[lane*3+2];
    float wp0=s_wp[lane*3+0], wp1=s_wp[lane*3+1], wp2=s_wp[lane*3+2];
    float bb=s_b[lane], sc=s_sc0[lane], bi=s_bi0[lane];
    float base = bb + wc0*cx + wc1*cy + wc2*cz;

    float m = -1e30f;
#pragma unroll
    for (int k = 0; k < KNN; k++) {
        int id = ip[k];                 // broadcast LDG
        float px = xb[id*3+0], py = xb[id*3+1], pz = xb[id*3+2];
        float h = base + wp0*px + wp1*py + wp2*pz;
        float y = gelu_exact(h * sc + bi);
        m = fmaxf(m, y);
    }

    // 32 -> 64 matmul via warp broadcast; lane owns outputs lane and lane+32
    float acc0 = 0.0f, acc1 = 0.0f;
#pragma unroll
    for (int cc = 0; cc < C0; cc++) {
        float xv = __shfl_sync(0xffffffffu, m, cc);
        acc0 += s_w1[lane*33 + cc] * xv;
        acc1 += s_w1[(lane+32)*33 + cc] * xv;
    }
    g_h1[(size_t)row*C1 + lane]      = acc0;
    g_h1[(size_t)row*C1 + lane + 32] = acc1;

    atomicAdd(&s_sum[lane],      acc0);
    atomicAdd(&s_ssq[lane],      acc0*acc0);
    atomicAdd(&s_sum[lane+32],   acc1);
    atomicAdd(&s_ssq[lane+32],   acc1*acc1);
    __syncthreads();
    if (t < C1) {
        int rep = blockIdx.x & (NB - 1);
        atomicAdd(&g_bins1[rep][t],      s_sum[t]);
        atomicAdd(&g_bins1[rep][C1 + t], s_ssq[t]);
    }
}

// ---------------- K3: BN1+GELU fused + z = y @ w2^T, 8x4 register tile ----------------
#define K3_R   32
#define K3_PAD (K3_R + 2)     // 34 floats/row: 8B-aligned row starts, low conflicts
__global__ __launch_bounds__(256)
void k3b(const float* __restrict__ g1, const float* __restrict__ be1)
{
    int t = threadIdx.x, lane = t & 31, w = t >> 5;
    int wc = w >> 2, wr = w & 3;            // warp-col (channels), warp-row (rows)
    int row0 = blockIdx.x * K3_R;
    int o0 = wc * 128 + lane * 4;           // 4 consecutive output channels
    int r0 = wr * 8;                        // 8 rows

    __shared__ float s_sc[C1], s_bi[C1];
    __shared__ float s_yT[C1][K3_PAD];
    __shared__ float s_sum[C2], s_ssq[C2];

    s_sum[t] = 0.0f; s_ssq[t] = 0.0f;
    if (t < C1) {
        float s = 0.0f, ss = 0.0f;
        for (int rep = 0; rep < NB; rep++) { s += g_bins1[rep][t]; ss += g_bins1[rep][C1+t]; }
        float inv = 1.0f / (float)NROWS;
        float mean = s * inv;
        float var  = ss * inv - mean * mean;
        float sc   = g1[t] * rsqrtf(var + EPSB);
        s_sc[t] = sc; s_bi[t] = be1[t] - mean * sc;
    }
    __syncthreads();

    // load h1 tile coalesced, BN1+GELU, store transposed [k][r]
#pragma unroll
    for (int i = 0; i < (K3_R*C1)/256; i++) {   // 8
        int j = t + i*256;
        int r = j >> 6, c = j & 63;
        float v = g_h1[(size_t)(row0 + r)*C1 + c];
        s_yT[c][r] = gelu_exact(v * s_sc[c] + s_bi[c]);
    }
    __syncthreads();

    unsigned long long acc[4][4];               // [channel j][row-pair p]
#pragma unroll
    for (int j = 0; j < 4; j++)
#pragma unroll
        for (int p = 0; p < 4; p++) acc[j][p] = 0ull;

    const float4* __restrict__ wt4 = reinterpret_cast<const float4*>(&g_w2T[0][0]);

#pragma unroll 16
    for (int k = 0; k < C1; k++) {
        const unsigned long long* yp =
            reinterpret_cast<const unsigned long long*>(&s_yT[k][r0]);
        unsigned long long y0 = yp[0], y1 = yp[1], y2 = yp[2], y3 = yp[3];
        float4 wv = wt4[k*(C2/4) + (o0 >> 2)];
        unsigned long long w0, w1, w2, w3;
        asm("mov.b64 %0, {%1, %1};" : "=l"(w0) : "f"(wv.x));
        asm("mov.b64 %0, {%1, %1};" : "=l"(w1) : "f"(wv.y));
        asm("mov.b64 %0, {%1, %1};" : "=l"(w2) : "f"(wv.z));
        asm("mov.b64 %0, {%1, %1};" : "=l"(w3) : "f"(wv.w));
        asm("fma.rn.f32x2 %0, %1, %2, %0;" : "+l"(acc[0][0]) : "l"(y0), "l"(w0));
        asm("fma.rn.f32x2 %0, %1, %2, %0;" : "+l"(acc[0][1]) : "l"(y1), "l"(w0));
        asm("fma.rn.f32x2 %0, %1, %2, %0;" : "+l"(acc[0][2]) : "l"(y2), "l"(w0));
        asm("fma.rn.f32x2 %0, %1, %2, %0;" : "+l"(acc[0][3]) : "l"(y3), "l"(w0));
        asm("fma.rn.f32x2 %0, %1, %2, %0;" : "+l"(acc[1][0]) : "l"(y0), "l"(w1));
        asm("fma.rn.f32x2 %0, %1, %2, %0;" : "+l"(acc[1][1]) : "l"(y1), "l"(w1));
        asm("fma.rn.f32x2 %0, %1, %2, %0;" : "+l"(acc[1][2]) : "l"(y2), "l"(w1));
        asm("fma.rn.f32x2 %0, %1, %2, %0;" : "+l"(acc[1][3]) : "l"(y3), "l"(w1));
        asm("fma.rn.f32x2 %0, %1, %2, %0;" : "+l"(acc[2][0]) : "l"(y0), "l"(w2));
        asm("fma.rn.f32x2 %0, %1, %2, %0;" : "+l"(acc[2][1]) : "l"(y1), "l"(w2));
        asm("fma.rn.f32x2 %0, %1, %2, %0;" : "+l"(acc[2][2]) : "l"(y2), "l"(w2));
        asm("fma.rn.f32x2 %0, %1, %2, %0;" : "+l"(acc[2][3]) : "l"(y3), "l"(w2));
        asm("fma.rn.f32x2 %0, %1, %2, %0;" : "+l"(acc[3][0]) : "l"(y0), "l"(w3));
        asm("fma.rn.f32x2 %0, %1, %2, %0;" : "+l"(acc[3][1]) : "l"(y1), "l"(w3));
        asm("fma.rn.f32x2 %0, %1, %2, %0;" : "+l"(acc[3][2]) : "l"(y2), "l"(w3));
        asm("fma.rn.f32x2 %0, %1, %2, %0;" : "+l"(acc[3][3]) : "l"(y3), "l"(w3));
    }

    // epilogue: store z (coalesced float4 per row) + per-channel partial stats
    float csum[4] = {0,0,0,0}, cssq[4] = {0,0,0,0};
#pragma unroll
    for (int p = 0; p < 4; p++) {
        float4 lo, hi;
        float zl[4], zh[4];
#pragma unroll
        for (int j = 0; j < 4; j++) {
            zl[j] = __uint_as_float((unsigned)(acc[j][p] & 0xffffffffull));
            zh[j] = __uint_as_float((unsigned)(acc[j][p] >> 32));
            csum[j] += zl[j] + zh[j];
            cssq[j] += zl[j]*zl[j] + zh[j]*zh[j];
        }
        lo.x=zl[0]; lo.y=zl[1]; lo.z=zl[2]; lo.w=zl[3];
        hi.x=zh[0]; hi.y=zh[1]; hi.z=zh[2]; hi.w=zh[3];
        int ra = row0 + r0 + 2*p;
        *reinterpret_cast<float4*>(&g_z[(size_t)ra*C2 + o0])     = lo;
        *reinterpret_cast<float4*>(&g_z[(size_t)(ra+1)*C2 + o0]) = hi;
    }
#pragma unroll
    for (int j = 0; j < 4; j++) {
        atomicAdd(&s_sum[o0 + j], csum[j]);
        atomicAdd(&s_ssq[o0 + j], cssq[j]);
    }
    __syncthreads();
    int rep = blockIdx.x & (NB - 1);
    atomicAdd(&g_bins2[rep][t],      s_sum[t]);
    atomicAdd(&g_bins2[rep][C2 + t], s_ssq[t]);
}

// ---------------- K4: BN2 normalize -> out ----------------
__global__ __launch_bounds__(256)
void k4(const float* __restrict__ g2, const float* __restrict__ be2,
        float* __restrict__ out)
{
    int t = threadIdx.x;
    __shared__ float s_sc[C2], s_bi[C2];
    {
        float s = 0.0f, ss = 0.0f;
        for (int rep = 0; rep < NB; rep++) { s += g_bins2[rep][t]; ss += g_bins2[rep][C2+t]; }
        float inv = 1.0f / (float)NROWS;
        float mean = s * inv;
        float var  = ss * inv - mean * mean;
        float sc   = g2[t] * rsqrtf(var + EPSB);
        s_sc[t] = sc; s_bi[t] = be2[t] - mean * sc;
    }
    __syncthreads();
    const float4* __restrict__ z4 = reinterpret_cast<const float4*>(g_z);
    float4* __restrict__ o4 = reinterpret_cast<float4*>(out);
    const int total4 = NROWS * C2 / 4;
    for (int i = blockIdx.x * 256 + t; i < total4; i += gridDim.x * 256) {
        float4 v = z4[i];
        int c = (i & 63) * 4;
        v.x = v.x * s_sc[c+0] + s_bi[c+0];
        v.y = v.y * s_sc[c+1] + s_bi[c+1];
        v.z = v.z * s_sc[c+2] + s_bi[c+2];
        v.w = v.w * s_sc[c+3] + s_bi[c+3];
        o4[i] = v;
    }
}

// ---------------- launch ----------------
extern "C" void kernel_launch(void* const* d_in, const int* in_sizes, int n_in,
                              void* d_out, int out_size)
{
    const float* centroid = (const float*)d_in[0];
    const float* xyz      = (const float*)d_in[1];
    const float* radius   = (const float*)d_in[2];
    const float* dist     = (const float*)d_in[3];
    const float* w_xyz    = (const float*)d_in[4];
    const float* b_xyz    = (const float*)d_in[5];
    const float* g0       = (const float*)d_in[6];
    const float* be0      = (const float*)d_in[7];
    const float* w1       = (const float*)d_in[8];
    const float* g1       = (const float*)d_in[9];
    const float* be1      = (const float*)d_in[10];
    const float* w2       = (const float*)d_in[11];
    const float* g2       = (const float*)d_in[12];
    const float* be2      = (const float*)d_in[13];
    float* out = (float*)d_out;

    k_zero<<<128, 256>>>(w2);
    k1_scan<<<NROWS, 256>>>(centroid, xyz, radius, dist, w_xyz, b_xyz);
    k2<<<NROWS / K2_ROWS, 256>>>(centroid, xyz, w_xyz, b_xyz, g0, be0, w1);
    k3b<<<NROWS / K3_R, 256>>>(g1, be1);
    k4<<<512, 256>>>(g2, be2, out);
}

// round 5
// speedup vs baseline: 1.9754x; 1.0326x over previous
#include <cuda_runtime.h>
#include <math.h>

#define BATCH 4
#define MROWS 2048
#define NPTS  8192
#define NROWS (BATCH*MROWS)   // 8192
#define KNN   20
#define C0    32
#define C1    64
#define C2    256
#define NB    32              // stat-bin replicas
#define EPSB  1e-5f

// ---------------- scratch (device globals; no allocation) ----------------
__device__ float g_bins0[NB][2*C0];
__device__ float g_bins1[NB][2*C1];
__device__ float g_bins2[NB][2*C2];
__device__ int   g_idx[NROWS*KNN];
__device__ float g_h1[NROWS*C1];
__device__ float g_w2T[C1][C2];       // transposed w2: [k][o]
__device__ float g_z[NROWS*C2];

__device__ __forceinline__ float gelu_exact(float x) {
    return 0.5f * x * (1.0f + erff(x * 0.70710678118654752f));
}

// ---------------- K0: zero stat bins + transpose w2 ----------------
__global__ void k_zero(const float* __restrict__ w2) {
    int i = blockIdx.x * blockDim.x + threadIdx.x;
    if (i < NB*2*C0) (&g_bins0[0][0])[i] = 0.0f;
    if (i < NB*2*C1) (&g_bins1[0][0])[i] = 0.0f;
    if (i < NB*2*C2) (&g_bins2[0][0])[i] = 0.0f;
    if (i < C1*C2) {
        int k = i >> 8, o = i & 255;
        g_w2T[k][o] = w2[o*C1 + k];
    }
}

// ---------------- K1: warp-per-row neighbor search + BN0 stats ----------------
#define K1_WARPS 8
__global__ __launch_bounds__(256)
void k1_scan(const float* __restrict__ centroid, const float* __restrict__ xyz,
             const float* __restrict__ radius,   const float* __restrict__ dist,
             const float* __restrict__ w_xyz,    const float* __restrict__ b_xyz)
{
    int t = threadIdx.x, lane = t & 31, w = t >> 5;
    int row = blockIdx.x * K1_WARPS + w;
    unsigned lmask = (1u << lane) - 1u;

    __shared__ int s_idx[K1_WARPS][KNN];

    float r = radius[row];
    const float* __restrict__ drow = dist + (size_t)row * NPTS;
    int cnt = 0;

    if (r >= 0.04f) {
        // fast path: 64-elem chunks, 1-deep prefetch; expected 1-3 iterations
        int base = 0;
        float d0 = drow[lane], d1 = drow[32 + lane];
        while (true) {
            int nb = base + 64;
            float n0 = 2.0f, n1 = 2.0f;
            if (nb < NPTS) { n0 = drow[nb + lane]; n1 = drow[nb + 32 + lane]; }
            unsigned m0 = __ballot_sync(0xffffffffu, d0 <= r);
            if (d0 <= r) {
                int pos = cnt + __popc(m0 & lmask);
                if (pos < KNN) s_idx[w][pos] = base + lane;
            }
            cnt += __popc(m0);
            unsigned m1 = __ballot_sync(0xffffffffu, d1 <= r);
            if (d1 <= r) {
                int pos = cnt + __popc(m1 & lmask);
                if (pos < KNN) s_idx[w][pos] = base + 32 + lane;
            }
            cnt += __popc(m1);
            if (cnt >= KNN || nb >= NPTS) break;
            base = nb; d0 = n0; d1 = n1;
        }
    } else {
        // slow path (rare): 256-elem chunks, 3-deep prefetch (MLP ~24)
        float buf[4][8];
#pragma unroll
        for (int q = 0; q < 4; q++)
#pragma unroll
            for (int s = 0; s < 8; s++) buf[q][s] = drow[q*256 + s*32 + lane];
        int base = 0;
#pragma unroll 1
        while (true) {
#pragma unroll
            for (int s = 0; s < 8; s++) {
                float d = buf[0][s];
                unsigned m = __ballot_sync(0xffffffffu, d <= r);
                if (d <= r) {
                    int pos = cnt + __popc(m & lmask);
                    if (pos < KNN) s_idx[w][pos] = base + s*32 + lane;
                }
                cnt += __popc(m);
            }
            if (cnt >= KNN || base + 256 >= NPTS) break;
            int nb = base + 1024;
#pragma unroll
            for (int q = 0; q < 3; q++)
#pragma unroll
                for (int s = 0; s < 8; s++) buf[q][s] = buf[q+1][s];
#pragma unroll
            for (int s = 0; s < 8; s++)
                buf[3][s] = (nb < NPTS) ? drow[nb + s*32 + lane] : 2.0f;
            base += 256;
        }
    }
    __syncwarp();

    // pad with first valid index (or N-1 clamp when none)
    if (lane < KNN) {
        int first = (cnt > 0) ? s_idx[w][0] : (NPTS - 1);
        int v = (lane < cnt) ? s_idx[w][lane] : first;
        s_idx[w][lane] = v;
        g_idx[row*KNN + lane] = v;
    }
    __syncwarp();

    // BN0 stats: lane = channel
    float a0=w_xyz[lane*9+0], a1=w_xyz[lane*9+1], a2=w_xyz[lane*9+2];
    float a3=w_xyz[lane*9+3], a4=w_xyz[lane*9+4], a5=w_xyz[lane*9+5];
    float a6=w_xyz[lane*9+6], a7=w_xyz[lane*9+7], a8=w_xyz[lane*9+8];
    float wc0=a0-a6, wc1=a1-a7, wc2=a2-a8;
    float wp0=a3+a6, wp1=a4+a7, wp2=a5+a8;
    float cx = centroid[row*3+0], cy = centroid[row*3+1], cz = centroid[row*3+2];
    const float* __restrict__ xb = xyz + (size_t)(row >> 11) * NPTS * 3;
    float hbase = b_xyz[lane] + wc0*cx + wc1*cy + wc2*cz;

    float ls = 0.0f, lss = 0.0f;
#pragma unroll
    for (int k = 0; k < KNN; k++) {
        int id = s_idx[w][k];           // warp-uniform -> broadcast
        float px = xb[id*3+0], py = xb[id*3+1], pz = xb[id*3+2];
        float h = hbase + wp0*px + wp1*py + wp2*pz;
        ls += h; lss += h*h;
    }
    int rep = row & (NB - 1);
    atomicAdd(&g_bins0[rep][lane],      ls);
    atomicAdd(&g_bins0[rep][C0 + lane], lss);
}

// ---------------- K2: warp-per-row BN0+GELU+max+w1 -> h1, BN1 stats ----------------
#define K2_ROWS 8          // one row per warp
__global__ __launch_bounds__(256)
void k2(const float* __restrict__ centroid, const float* __restrict__ xyz,
        const float* __restrict__ w_xyz,    const float* __restrict__ b_xyz,
        const float* __restrict__ g0,       const float* __restrict__ be0,
        const float* __restrict__ w1)
{
    int t = threadIdx.x, lane = t & 31, w = t >> 5;
    __shared__ float s_wc[C0*3], s_wp[C0*3], s_b[C0];
    __shared__ float s_sc0[C0], s_bi0[C0];
    __shared__ float s_w1[C1*33];
    __shared__ float s_sum[C1], s_ssq[C1];

    if (t < C0) {
        float a0=w_xyz[t*9+0], a1=w_xyz[t*9+1], a2=w_xyz[t*9+2];
        float a3=w_xyz[t*9+3], a4=w_xyz[t*9+4], a5=w_xyz[t*9+5];
        float a6=w_xyz[t*9+6], a7=w_xyz[t*9+7], a8=w_xyz[t*9+8];
        s_wc[t*3+0]=a0-a6; s_wc[t*3+1]=a1-a7; s_wc[t*3+2]=a2-a8;
        s_wp[t*3+0]=a3+a6; s_wp[t*3+1]=a4+a7; s_wp[t*3+2]=a5+a8;
        s_b[t]=b_xyz[t];
        float s = 0.0f, ss = 0.0f;
        for (int rep = 0; rep < NB; rep++) { s += g_bins0[rep][t]; ss += g_bins0[rep][C0+t]; }
        float inv = 1.0f / (float)(NROWS * KNN);
        float mean = s * inv;
        float var  = ss * inv - mean * mean;
        float sc   = g0[t] * rsqrtf(var + EPSB);
        s_sc0[t] = sc; s_bi0[t] = be0[t] - mean * sc;
    }
    for (int i = t; i < C1*C0; i += 256) {
        int o = i >> 5, cc = i & 31;
        s_w1[o*33 + cc] = w1[i];
    }
    if (t < C1) { s_sum[t] = 0.0f; s_ssq[t] = 0.0f; }
    __syncthreads();

    int row = blockIdx.x * K2_ROWS + w;
    float cx = centroid[row*3+0], cy = centroid[row*3+1], cz = centroid[row*3+2];
    const float* __restrict__ xb = xyz + (size_t)(row >> 11) * NPTS * 3;
    const int* __restrict__ ip = &g_idx[row*KNN];

    float wc0=s_wc[lane*3+0], wc1=s_wc[lane*3+1], wc2=s_wc[lane*3+2];
    float wp0=s_wp[lane*3+0], wp1=s_wp[lane*3+1], wp2=s_wp[lane*3+2];
    float bb=s_b[lane], sc=s_sc0[lane], bi=s_bi0[lane];
    float base = bb + wc0*cx + wc1*cy + wc2*cz;

    float m = -1e30f;
#pragma unroll
    for (int k = 0; k < KNN; k++) {
        int id = ip[k];                 // broadcast LDG
        float px = xb[id*3+0], py = xb[id*3+1], pz = xb[id*3+2];
        float h = base + wp0*px + wp1*py + wp2*pz;
        float y = gelu_exact(h * sc + bi);
        m = fmaxf(m, y);
    }

    // 32 -> 64 matmul via warp broadcast; lane owns outputs lane and lane+32
    float acc0 = 0.0f, acc1 = 0.0f;
#pragma unroll
    for (int cc = 0; cc < C0; cc++) {
        float xv = __shfl_sync(0xffffffffu, m, cc);
        acc0 += s_w1[lane*33 + cc] * xv;
        acc1 += s_w1[(lane+32)*33 + cc] * xv;
    }
    g_h1[(size_t)row*C1 + lane]      = acc0;
    g_h1[(size_t)row*C1 + lane + 32] = acc1;

    atomicAdd(&s_sum[lane],      acc0);
    atomicAdd(&s_ssq[lane],      acc0*acc0);
    atomicAdd(&s_sum[lane+32],   acc1);
    atomicAdd(&s_ssq[lane+32],   acc1*acc1);
    __syncthreads();
    if (t < C1) {
        int rep = blockIdx.x & (NB - 1);
        atomicAdd(&g_bins1[rep][t],      s_sum[t]);
        atomicAdd(&g_bins1[rep][C1 + t], s_ssq[t]);
    }
}

// ---------------- K3: BN1+GELU fused + z = y @ w2^T, 4x4 register tile ----------------
#define K3_R   16
#define K3_PAD (K3_R + 2)     // 18 floats/row: 72B row stride, 8B-aligned row starts
__global__ __launch_bounds__(256)
void k3b(const float* __restrict__ g1, const float* __restrict__ be1)
{
    int t = threadIdx.x, lane = t & 31, w = t >> 5;
    int wcg = w >> 2, wr = w & 3;           // channel-half, row-group
    int row0 = blockIdx.x * K3_R;
    int o0 = wcg * 128 + lane * 4;          // 4 consecutive output channels
    int r0 = wr * 4;                        // 4 rows

    __shared__ float s_sc[C1], s_bi[C1];
    __shared__ float s_yT[C1][K3_PAD];
    __shared__ float s_sum[C2], s_ssq[C2];

    s_sum[t] = 0.0f; s_ssq[t] = 0.0f;
    if (t < C1) {
        float s = 0.0f, ss = 0.0f;
        for (int rep = 0; rep < NB; rep++) { s += g_bins1[rep][t]; ss += g_bins1[rep][C1+t]; }
        float inv = 1.0f / (float)NROWS;
        float mean = s * inv;
        float var  = ss * inv - mean * mean;
        float sc   = g1[t] * rsqrtf(var + EPSB);
        s_sc[t] = sc; s_bi[t] = be1[t] - mean * sc;
    }
    __syncthreads();

    // load h1 tile coalesced, BN1+GELU, store transposed [k][r]
#pragma unroll
    for (int i = 0; i < (K3_R*C1)/256; i++) {   // 4
        int j = t + i*256;
        int r = j >> 6, c = j & 63;
        float v = g_h1[(size_t)(row0 + r)*C1 + c];
        s_yT[c][r] = gelu_exact(v * s_sc[c] + s_bi[c]);
    }
    __syncthreads();

    unsigned long long acc[4][2];               // [channel j][row-pair p]
#pragma unroll
    for (int j = 0; j < 4; j++)
#pragma unroll
        for (int p = 0; p < 2; p++) acc[j][p] = 0ull;

    const float4* __restrict__ wt4 = reinterpret_cast<const float4*>(&g_w2T[0][0]);

#pragma unroll
    for (int k = 0; k < C1; k++) {
        const unsigned long long* yp =
            reinterpret_cast<const unsigned long long*>(&s_yT[k][r0]);
        unsigned long long y0 = yp[0], y1 = yp[1];
        float4 wv = wt4[k*(C2/4) + (o0 >> 2)];
        unsigned long long w0, w1, w2, w3;
        asm("mov.b64 %0, {%1, %1};" : "=l"(w0) : "f"(wv.x));
        asm("mov.b64 %0, {%1, %1};" : "=l"(w1) : "f"(wv.y));
        asm("mov.b64 %0, {%1, %1};" : "=l"(w2) : "f"(wv.z));
        asm("mov.b64 %0, {%1, %1};" : "=l"(w3) : "f"(wv.w));
        asm("fma.rn.f32x2 %0, %1, %2, %0;" : "+l"(acc[0][0]) : "l"(y0), "l"(w0));
        asm("fma.rn.f32x2 %0, %1, %2, %0;" : "+l"(acc[0][1]) : "l"(y1), "l"(w0));
        asm("fma.rn.f32x2 %0, %1, %2, %0;" : "+l"(acc[1][0]) : "l"(y0), "l"(w1));
        asm("fma.rn.f32x2 %0, %1, %2, %0;" : "+l"(acc[1][1]) : "l"(y1), "l"(w1));
        asm("fma.rn.f32x2 %0, %1, %2, %0;" : "+l"(acc[2][0]) : "l"(y0), "l"(w2));
        asm("fma.rn.f32x2 %0, %1, %2, %0;" : "+l"(acc[2][1]) : "l"(y1), "l"(w2));
        asm("fma.rn.f32x2 %0, %1, %2, %0;" : "+l"(acc[3][0]) : "l"(y0), "l"(w3));
        asm("fma.rn.f32x2 %0, %1, %2, %0;" : "+l"(acc[3][1]) : "l"(y1), "l"(w3));
    }

    // epilogue: store z (coalesced float4 per row) + per-channel partial stats
    float csum[4] = {0,0,0,0}, cssq[4] = {0,0,0,0};
#pragma unroll
    for (int p = 0; p < 2; p++) {
        float4 lo, hi;
        float zl[4], zh[4];
#pragma unroll
        for (int j = 0; j < 4; j++) {
            zl[j] = __uint_as_float((unsigned)(acc[j][p] & 0xffffffffull));
            zh[j] = __uint_as_float((unsigned)(acc[j][p] >> 32));
            csum[j] += zl[j] + zh[j];
            cssq[j] += zl[j]*zl[j] + zh[j]*zh[j];
        }
        lo.x=zl[0]; lo.y=zl[1]; lo.z=zl[2]; lo.w=zl[3];
        hi.x=zh[0]; hi.y=zh[1]; hi.z=zh[2]; hi.w=zh[3];
        int ra = row0 + r0 + 2*p;
        *reinterpret_cast<float4*>(&g_z[(size_t)ra*C2 + o0])     = lo;
        *reinterpret_cast<float4*>(&g_z[(size_t)(ra+1)*C2 + o0]) = hi;
    }
#pragma unroll
    for (int j = 0; j < 4; j++) {
        atomicAdd(&s_sum[o0 + j], csum[j]);
        atomicAdd(&s_ssq[o0 + j], cssq[j]);
    }
    __syncthreads();
    int rep = blockIdx.x & (NB - 1);
    atomicAdd(&g_bins2[rep][t],      s_sum[t]);
    atomicAdd(&g_bins2[rep][C2 + t], s_ssq[t]);
}

// ---------------- K4: BN2 normalize -> out ----------------
__global__ __launch_bounds__(256)
void k4(const float* __restrict__ g2, const float* __restrict__ be2,
        float* __restrict__ out)
{
    int t = threadIdx.x;
    __shared__ float s_sc[C2], s_bi[C2];
    {
        float s = 0.0f, ss = 0.0f;
        for (int rep = 0; rep < NB; rep++) { s += g_bins2[rep][t]; ss += g_bins2[rep][C2+t]; }
        float inv = 1.0f / (float)NROWS;
        float mean = s * inv;
        float var  = ss * inv - mean * mean;
        float sc   = g2[t] * rsqrtf(var + EPSB);
        s_sc[t] = sc; s_bi[t] = be2[t] - mean * sc;
    }
    __syncthreads();
    const float4* __restrict__ z4 = reinterpret_cast<const float4*>(g_z);
    float4* __restrict__ o4 = reinterpret_cast<float4*>(out);
    const int total4 = NROWS * C2 / 4;
    for (int i = blockIdx.x * 256 + t; i < total4; i += gridDim.x * 256) {
        float4 v = z4[i];
        int c = (i & 63) * 4;
        v.x = v.x * s_sc[c+0] + s_bi[c+0];
        v.y = v.y * s_sc[c+1] + s_bi[c+1];
        v.z = v.z * s_sc[c+2] + s_bi[c+2];
        v.w = v.w * s_sc[c+3] + s_bi[c+3];
        o4[i] = v;
    }
}

// ---------------- launch ----------------
extern "C" void kernel_launch(void* const* d_in, const int* in_sizes, int n_in,
                              void* d_out, int out_size)
{
    const float* centroid = (const float*)d_in[0];
    const float* xyz      = (const float*)d_in[1];
    const float* radius   = (const float*)d_in[2];
    const float* dist     = (const float*)d_in[3];
    const float* w_xyz    = (const float*)d_in[4];
    const float* b_xyz    = (const float*)d_in[5];
    const float* g0       = (const float*)d_in[6];
    const float* be0      = (const float*)d_in[7];
    const float* w1       = (const float*)d_in[8];
    const float* g1       = (const float*)d_in[9];
    const float* be1      = (const float*)d_in[10];
    const float* w2       = (const float*)d_in[11];
    const float* g2       = (const float*)d_in[12];
    const float* be2      = (const float*)d_in[13];
    float* out = (float*)d_out;

    k_zero<<<128, 256>>>(w2);
    k1_scan<<<NROWS / K1_WARPS, 256>>>(centroid, xyz, radius, dist, w_xyz, b_xyz);
    k2<<<NROWS / K2_ROWS, 256>>>(centroid, xyz, w_xyz, b_xyz, g0, be0, w1);
    k3b<<<NROWS / K3_R, 256>>>(g1, be1);
    k4<<<512, 256>>>(g2, be2, out);
}

// round 6
// speedup vs baseline: 2.2287x; 1.1282x over previous
#include <cuda_runtime.h>
#include <math.h>

#define BATCH 4
#define MROWS 2048
#define NPTS  8192
#define NROWS (BATCH*MROWS)   // 8192
#define KNN   20
#define C0    32
#define C1    64
#define C2    256
#define NB    32              // stat-bin replicas
#define EPSB  1e-5f

// ---------------- scratch (device globals; no allocation) ----------------
__device__ float g_bins0[NB][2*C0];
__device__ float g_bins1[NB][2*C1];
__device__ float g_bins2[NB][2*C2];
__device__ int   g_idx[NROWS*KNN];
__device__ float g_h1[NROWS*C1];
__device__ float g_w2T[C1][C2];       // transposed w2: [k][o]
__device__ float g_z[NROWS*C2];

__device__ __forceinline__ float gelu_exact(float x) {
    return 0.5f * x * (1.0f + erff(x * 0.70710678118654752f));
}

// ---------------- K0: zero stat bins + transpose w2 ----------------
__global__ void k_zero(const float* __restrict__ w2) {
    int i = blockIdx.x * blockDim.x + threadIdx.x;
    if (i < NB*2*C0) (&g_bins0[0][0])[i] = 0.0f;
    if (i < NB*2*C1) (&g_bins1[0][0])[i] = 0.0f;
    if (i < NB*2*C2) (&g_bins2[0][0])[i] = 0.0f;
    if (i < C1*C2) {
        int k = i >> 8, o = i & 255;
        g_w2T[k][o] = w2[o*C1 + k];
    }
}

// ---------------- K1: warp-per-row neighbor search + BN0 stats ----------------
#define K1_WARPS 8
__global__ __launch_bounds__(256)
void k1_scan(const float* __restrict__ centroid, const float* __restrict__ xyz,
             const float* __restrict__ radius,   const float* __restrict__ dist,
             const float* __restrict__ w_xyz,    const float* __restrict__ b_xyz)
{
    int t = threadIdx.x, lane = t & 31, w = t >> 5;
    int row = blockIdx.x * K1_WARPS + w;
    unsigned lmask = (1u << lane) - 1u;

    __shared__ int s_idx[K1_WARPS][KNN];

    float r = radius[row];
    const float* __restrict__ drow = dist + (size_t)row * NPTS;
    int cnt = 0;

    if (r >= 0.04f) {
        // fast path: 64-elem chunks, 1-deep prefetch; expected 1-3 iterations
        int base = 0;
        float d0 = drow[lane], d1 = drow[32 + lane];
        while (true) {
            int nb = base + 64;
            float n0 = 2.0f, n1 = 2.0f;
            if (nb < NPTS) { n0 = drow[nb + lane]; n1 = drow[nb + 32 + lane]; }
            unsigned m0 = __ballot_sync(0xffffffffu, d0 <= r);
            if (d0 <= r) {
                int pos = cnt + __popc(m0 & lmask);
                if (pos < KNN) s_idx[w][pos] = base + lane;
            }
            cnt += __popc(m0);
            unsigned m1 = __ballot_sync(0xffffffffu, d1 <= r);
            if (d1 <= r) {
                int pos = cnt + __popc(m1 & lmask);
                if (pos < KNN) s_idx[w][pos] = base + 32 + lane;
            }
            cnt += __popc(m1);
            if (cnt >= KNN || nb >= NPTS) break;
            base = nb; d0 = n0; d1 = n1;
        }
    } else {
        // slow path (rare): 256-elem chunks, 3-deep prefetch (MLP ~24)
        float buf[4][8];
#pragma unroll
        for (int q = 0; q < 4; q++)
#pragma unroll
            for (int s = 0; s < 8; s++) buf[q][s] = drow[q*256 + s*32 + lane];
        int base = 0;
#pragma unroll 1
        while (true) {
#pragma unroll
            for (int s = 0; s < 8; s++) {
                float d = buf[0][s];
                unsigned m = __ballot_sync(0xffffffffu, d <= r);
                if (d <= r) {
                    int pos = cnt + __popc(m & lmask);
                    if (pos < KNN) s_idx[w][pos] = base + s*32 + lane;
                }
                cnt += __popc(m);
            }
            if (cnt >= KNN || base + 256 >= NPTS) break;
            int nb = base + 1024;
#pragma unroll
            for (int q = 0; q < 3; q++)
#pragma unroll
                for (int s = 0; s < 8; s++) buf[q][s] = buf[q+1][s];
#pragma unroll
            for (int s = 0; s < 8; s++)
                buf[3][s] = (nb < NPTS) ? drow[nb + s*32 + lane] : 2.0f;
            base += 256;
        }
    }
    __syncwarp();

    // pad with first valid index (or N-1 clamp when none)
    if (lane < KNN) {
        int first = (cnt > 0) ? s_idx[w][0] : (NPTS - 1);
        int v = (lane < cnt) ? s_idx[w][lane] : first;
        s_idx[w][lane] = v;
        g_idx[row*KNN + lane] = v;
    }
    __syncwarp();

    // BN0 stats: lane = channel
    float a0=w_xyz[lane*9+0], a1=w_xyz[lane*9+1], a2=w_xyz[lane*9+2];
    float a3=w_xyz[lane*9+3], a4=w_xyz[lane*9+4], a5=w_xyz[lane*9+5];
    float a6=w_xyz[lane*9+6], a7=w_xyz[lane*9+7], a8=w_xyz[lane*9+8];
    float wc0=a0-a6, wc1=a1-a7, wc2=a2-a8;
    float wp0=a3+a6, wp1=a4+a7, wp2=a5+a8;
    float cx = centroid[row*3+0], cy = centroid[row*3+1], cz = centroid[row*3+2];
    const float* __restrict__ xb = xyz + (size_t)(row >> 11) * NPTS * 3;
    float hbase = b_xyz[lane] + wc0*cx + wc1*cy + wc2*cz;

    float ls = 0.0f, lss = 0.0f;
#pragma unroll
    for (int k = 0; k < KNN; k++) {
        int id = s_idx[w][k];           // warp-uniform -> broadcast
        float px = xb[id*3+0], py = xb[id*3+1], pz = xb[id*3+2];
        float h = hbase + wp0*px + wp1*py + wp2*pz;
        ls += h; lss += h*h;
    }
    int rep = row & (NB - 1);
    atomicAdd(&g_bins0[rep][lane],      ls);
    atomicAdd(&g_bins0[rep][C0 + lane], lss);
}

// ---------------- K2: warp-per-row BN0+GELU+max+w1 -> h1, BN1 stats ----------------
// GELU is unimodal (min at x~-0.7518), so max_k gelu(a_k) =
// max(gelu(min_k a_k), gelu(max_k a_k)) -- only 2 erff per (row,channel).
#define K2_ROWS 8          // one row per warp
__global__ __launch_bounds__(256)
void k2(const float* __restrict__ centroid, const float* __restrict__ xyz,
        const float* __restrict__ w_xyz,    const float* __restrict__ b_xyz,
        const float* __restrict__ g0,       const float* __restrict__ be0,
        const float* __restrict__ w1)
{
    int t = threadIdx.x, lane = t & 31, w = t >> 5;
    __shared__ float s_wc[C0*3], s_wp[C0*3], s_b[C0];
    __shared__ float s_sc0[C0], s_bi0[C0];
    __shared__ float s_w1[C1*33];
    __shared__ float s_sum[C1], s_ssq[C1];

    if (t < C0) {
        float a0=w_xyz[t*9+0], a1=w_xyz[t*9+1], a2=w_xyz[t*9+2];
        float a3=w_xyz[t*9+3], a4=w_xyz[t*9+4], a5=w_xyz[t*9+5];
        float a6=w_xyz[t*9+6], a7=w_xyz[t*9+7], a8=w_xyz[t*9+8];
        s_wc[t*3+0]=a0-a6; s_wc[t*3+1]=a1-a7; s_wc[t*3+2]=a2-a8;
        s_wp[t*3+0]=a3+a6; s_wp[t*3+1]=a4+a7; s_wp[t*3+2]=a5+a8;
        s_b[t]=b_xyz[t];
        float s = 0.0f, ss = 0.0f;
        for (int rep = 0; rep < NB; rep++) { s += g_bins0[rep][t]; ss += g_bins0[rep][C0+t]; }
        float inv = 1.0f / (float)(NROWS * KNN);
        float mean = s * inv;
        float var  = ss * inv - mean * mean;
        float sc   = g0[t] * rsqrtf(var + EPSB);
        s_sc0[t] = sc; s_bi0[t] = be0[t] - mean * sc;
    }
    for (int i = t; i < C1*C0; i += 256) {
        int o = i >> 5, cc = i & 31;
        s_w1[o*33 + cc] = w1[i];
    }
    if (t < C1) { s_sum[t] = 0.0f; s_ssq[t] = 0.0f; }
    __syncthreads();

    int row = blockIdx.x * K2_ROWS + w;
    float cx = centroid[row*3+0], cy = centroid[row*3+1], cz = centroid[row*3+2];
    const float* __restrict__ xb = xyz + (size_t)(row >> 11) * NPTS * 3;
    const int* __restrict__ ip = &g_idx[row*KNN];

    float wc0=s_wc[lane*3+0], wc1=s_wc[lane*3+1], wc2=s_wc[lane*3+2];
    float wp0=s_wp[lane*3+0], wp1=s_wp[lane*3+1], wp2=s_wp[lane*3+2];
    float bb=s_b[lane], sc=s_sc0[lane], bi=s_bi0[lane];
    float base = bb + wc0*cx + wc1*cy + wc2*cz;

    float hmin = 1e30f, hmax = -1e30f;
#pragma unroll
    for (int k = 0; k < KNN; k++) {
        int id = ip[k];                 // broadcast LDG
        float px = xb[id*3+0], py = xb[id*3+1], pz = xb[id*3+2];
        float h = base + wp0*px + wp1*py + wp2*pz;
        hmin = fminf(hmin, h);
        hmax = fmaxf(hmax, h);
    }
    float e0 = hmin * sc + bi;
    float e1 = hmax * sc + bi;
    float lo = fminf(e0, e1), hi = fmaxf(e0, e1);
    float m = fmaxf(gelu_exact(lo), gelu_exact(hi));

    // 32 -> 64 matmul via warp broadcast; lane owns outputs lane and lane+32
    float acc0 = 0.0f, acc1 = 0.0f;
#pragma unroll
    for (int cc = 0; cc < C0; cc++) {
        float xv = __shfl_sync(0xffffffffu, m, cc);
        acc0 += s_w1[lane*33 + cc] * xv;
        acc1 += s_w1[(lane+32)*33 + cc] * xv;
    }
    g_h1[(size_t)row*C1 + lane]      = acc0;
    g_h1[(size_t)row*C1 + lane + 32] = acc1;

    atomicAdd(&s_sum[lane],      acc0);
    atomicAdd(&s_ssq[lane],      acc0*acc0);
    atomicAdd(&s_sum[lane+32],   acc1);
    atomicAdd(&s_ssq[lane+32],   acc1*acc1);
    __syncthreads();
    if (t < C1) {
        int rep = blockIdx.x & (NB - 1);
        atomicAdd(&g_bins1[rep][t],      s_sum[t]);
        atomicAdd(&g_bins1[rep][C1 + t], s_ssq[t]);
    }
}

// ---------------- K3: BN1+GELU fused + z = y @ w2^T, 8x4 register tile ----------------
#define K3_R   32
#define K3_PAD (K3_R + 2)     // 34 floats/row: 8B-aligned row starts, low conflicts
__global__ __launch_bounds__(256)
void k3b(const float* __restrict__ g1, const float* __restrict__ be1)
{
    int t = threadIdx.x, lane = t & 31, w = t >> 5;
    int wc = w >> 2, wr = w & 3;            // warp-col (channels), warp-row (rows)
    int row0 = blockIdx.x * K3_R;
    int o0 = wc * 128 + lane * 4;           // 4 consecutive output channels
    int r0 = wr * 8;                        // 8 rows

    __shared__ float s_sc[C1], s_bi[C1];
    __shared__ float s_yT[C1][K3_PAD];
    __shared__ float s_sum[C2], s_ssq[C2];

    s_sum[t] = 0.0f; s_ssq[t] = 0.0f;
    if (t < C1) {
        float s = 0.0f, ss = 0.0f;
        for (int rep = 0; rep < NB; rep++) { s += g_bins1[rep][t]; ss += g_bins1[rep][C1+t]; }
        float inv = 1.0f / (float)NROWS;
        float mean = s * inv;
        float var  = ss * inv - mean * mean;
        float sc   = g1[t] * rsqrtf(var + EPSB);
        s_sc[t] = sc; s_bi[t] = be1[t] - mean * sc;
    }
    __syncthreads();

    // load h1 tile coalesced, BN1+GELU, store transposed [k][r]
#pragma unroll
    for (int i = 0; i < (K3_R*C1)/256; i++) {   // 8
        int j = t + i*256;
        int r = j >> 6, c = j & 63;
        float v = g_h1[(size_t)(row0 + r)*C1 + c];
        s_yT[c][r] = gelu_exact(v * s_sc[c] + s_bi[c]);
    }
    __syncthreads();

    unsigned long long acc[4][4];               // [channel j][row-pair p]
#pragma unroll
    for (int j = 0; j < 4; j++)
#pragma unroll
        for (int p = 0; p < 4; p++) acc[j][p] = 0ull;

    const float4* __restrict__ wt4 = reinterpret_cast<const float4*>(&g_w2T[0][0]);

#pragma unroll 16
    for (int k = 0; k < C1; k++) {
        const unsigned long long* yp =
            reinterpret_cast<const unsigned long long*>(&s_yT[k][r0]);
        unsigned long long y0 = yp[0], y1 = yp[1], y2 = yp[2], y3 = yp[3];
        float4 wv = wt4[k*(C2/4) + (o0 >> 2)];
        unsigned long long w0, w1, w2, w3;
        asm("mov.b64 %0, {%1, %1};" : "=l"(w0) : "f"(wv.x));
        asm("mov.b64 %0, {%1, %1};" : "=l"(w1) : "f"(wv.y));
        asm("mov.b64 %0, {%1, %1};" : "=l"(w2) : "f"(wv.z));
        asm("mov.b64 %0, {%1, %1};" : "=l"(w3) : "f"(wv.w));
        asm("fma.rn.f32x2 %0, %1, %2, %0;" : "+l"(acc[0][0]) : "l"(y0), "l"(w0));
        asm("fma.rn.f32x2 %0, %1, %2, %0;" : "+l"(acc[0][1]) : "l"(y1), "l"(w0));
        asm("fma.rn.f32x2 %0, %1, %2, %0;" : "+l"(acc[0][2]) : "l"(y2), "l"(w0));
        asm("fma.rn.f32x2 %0, %1, %2, %0;" : "+l"(acc[0][3]) : "l"(y3), "l"(w0));
        asm("fma.rn.f32x2 %0, %1, %2, %0;" : "+l"(acc[1][0]) : "l"(y0), "l"(w1));
        asm("fma.rn.f32x2 %0, %1, %2, %0;" : "+l"(acc[1][1]) : "l"(y1), "l"(w1));
        asm("fma.rn.f32x2 %0, %1, %2, %0;" : "+l"(acc[1][2]) : "l"(y2), "l"(w1));
        asm("fma.rn.f32x2 %0, %1, %2, %0;" : "+l"(acc[1][3]) : "l"(y3), "l"(w1));
        asm("fma.rn.f32x2 %0, %1, %2, %0;" : "+l"(acc[2][0]) : "l"(y0), "l"(w2));
        asm("fma.rn.f32x2 %0, %1, %2, %0;" : "+l"(acc[2][1]) : "l"(y1), "l"(w2));
        asm("fma.rn.f32x2 %0, %1, %2, %0;" : "+l"(acc[2][2]) : "l"(y2), "l"(w2));
        asm("fma.rn.f32x2 %0, %1, %2, %0;" : "+l"(acc[2][3]) : "l"(y3), "l"(w2));
        asm("fma.rn.f32x2 %0, %1, %2, %0;" : "+l"(acc[3][0]) : "l"(y0), "l"(w3));
        asm("fma.rn.f32x2 %0, %1, %2, %0;" : "+l"(acc[3][1]) : "l"(y1), "l"(w3));
        asm("fma.rn.f32x2 %0, %1, %2, %0;" : "+l"(acc[3][2]) : "l"(y2), "l"(w3));
        asm("fma.rn.f32x2 %0, %1, %2, %0;" : "+l"(acc[3][3]) : "l"(y3), "l"(w3));
    }

    // epilogue: store z (coalesced float4 per row) + per-channel partial stats
    float csum[4] = {0,0,0,0}, cssq[4] = {0,0,0,0};
#pragma unroll
    for (int p = 0; p < 4; p++) {
        float4 lo, hi;
        float zl[4], zh[4];
#pragma unroll
        for (int j = 0; j < 4; j++) {
            zl[j] = __uint_as_float((unsigned)(acc[j][p] & 0xffffffffull));
            zh[j] = __uint_as_float((unsigned)(acc[j][p] >> 32));
            csum[j] += zl[j] + zh[j];
            cssq[j] += zl[j]*zl[j] + zh[j]*zh[j];
        }
        lo.x=zl[0]; lo.y=zl[1]; lo.z=zl[2]; lo.w=zl[3];
        hi.x=zh[0]; hi.y=zh[1]; hi.z=zh[2]; hi.w=zh[3];
        int ra = row0 + r0 + 2*p;
        *reinterpret_cast<float4*>(&g_z[(size_t)ra*C2 + o0])     = lo;
        *reinterpret_cast<float4*>(&g_z[(size_t)(ra+1)*C2 + o0]) = hi;
    }
#pragma unroll
    for (int j = 0; j < 4; j++) {
        atomicAdd(&s_sum[o0 + j], csum[j]);
        atomicAdd(&s_ssq[o0 + j], cssq[j]);
    }
    __syncthreads();
    int rep = blockIdx.x & (NB - 1);
    atomicAdd(&g_bins2[rep][t],      s_sum[t]);
    atomicAdd(&g_bins2[rep][C2 + t], s_ssq[t]);
}

// ---------------- K4: BN2 normalize -> out ----------------
__global__ __launch_bounds__(256)
void k4(const float* __restrict__ g2, const float* __restrict__ be2,
        float* __restrict__ out)
{
    int t = threadIdx.x;
    __shared__ float s_sc[C2], s_bi[C2];
    {
        float s = 0.0f, ss = 0.0f;
        for (int rep = 0; rep < NB; rep++) { s += g_bins2[rep][t]; ss += g_bins2[rep][C2+t]; }
        float inv = 1.0f / (float)NROWS;
        float mean = s * inv;
        float var  = ss * inv - mean * mean;
        float sc   = g2[t] * rsqrtf(var + EPSB);
        s_sc[t] = sc; s_bi[t] = be2[t] - mean * sc;
    }
    __syncthreads();
    const float4* __restrict__ z4 = reinterpret_cast<const float4*>(g_z);
    float4* __restrict__ o4 = reinterpret_cast<float4*>(out);
    const int total4 = NROWS * C2 / 4;
    for (int i = blockIdx.x * 256 + t; i < total4; i += gridDim.x * 256) {
        float4 v = z4[i];
        int c = (i & 63) * 4;
        v.x = v.x * s_sc[c+0] + s_bi[c+0];
        v.y = v.y * s_sc[c+1] + s_bi[c+1];
        v.z = v.z * s_sc[c+2] + s_bi[c+2];
        v.w = v.w * s_sc[c+3] + s_bi[c+3];
        o4[i] = v;
    }
}

// ---------------- launch ----------------
extern "C" void kernel_launch(void* const* d_in, const int* in_sizes, int n_in,
                              void* d_out, int out_size)
{
    const float* centroid = (const float*)d_in[0];
    const float* xyz      = (const float*)d_in[1];
    const float* radius   = (const float*)d_in[2];
    const float* dist     = (const float*)d_in[3];
    const float* w_xyz    = (const float*)d_in[4];
    const float* b_xyz    = (const float*)d_in[5];
    const float* g0       = (const float*)d_in[6];
    const float* be0      = (const float*)d_in[7];
    const float* w1       = (const float*)d_in[8];
    const float* g1       = (const float*)d_in[9];
    const float* be1      = (const float*)d_in[10];
    const float* w2       = (const float*)d_in[11];
    const float* g2       = (const float*)d_in[12];
    const float* be2      = (const float*)d_in[13];
    float* out = (float*)d_out;

    k_zero<<<128, 256>>>(w2);
    k1_scan<<<NROWS / K1_WARPS, 256>>>(centroid, xyz, radius, dist, w_xyz, b_xyz);
    k2<<<NROWS / K2_ROWS, 256>>>(centroid, xyz, w_xyz, b_xyz, g0, be0, w1);
    k3b<<<NROWS / K3_R, 256>>>(g1, be1);
    k4<<<512, 256>>>(g2, be2, out);
}

// round 7
// speedup vs baseline: 2.4291x; 1.0899x over previous
#include <cuda_runtime.h>
#include <math.h>

#define BATCH 4
#define MROWS 2048
#define NPTS  8192
#define NROWS (BATCH*MROWS)   // 8192
#define KNN   20
#define C0    32
#define C1    64
#define C2    256
#define NB    32              // stat-bin replicas
#define EPSB  1e-5f

// ---------------- scratch (device globals; no allocation) ----------------
__device__ float g_bins0[NB][2*C0];
__device__ float g_bins1[NB][2*C1];
__device__ float g_bins2[NB][2*C2];
__device__ float g_hmm[NROWS][2][C0];   // per (row,channel) pre-BN0 min/max
__device__ float g_h1[NROWS*C1];
__device__ float g_w2T[C1][C2];         // transposed w2: [k][o]
__device__ float g_z[NROWS*C2];

__device__ __forceinline__ float gelu_exact(float x) {
    return 0.5f * x * (1.0f + erff(x * 0.70710678118654752f));
}

// ---------------- K0: zero stat bins + transpose w2 ----------------
__global__ void k_zero(const float* __restrict__ w2) {
    int i = blockIdx.x * blockDim.x + threadIdx.x;
    if (i < NB*2*C0) (&g_bins0[0][0])[i] = 0.0f;
    if (i < NB*2*C1) (&g_bins1[0][0])[i] = 0.0f;
    if (i < NB*2*C2) (&g_bins2[0][0])[i] = 0.0f;
    if (i < C1*C2) {
        int k = i >> 8, o = i & 255;
        g_w2T[k][o] = w2[o*C1 + k];
    }
}

// ---------------- K1: warp-per-row neighbor search + BN0 stats + h min/max ----------------
#define K1_WARPS 8
__global__ __launch_bounds__(256)
void k1_scan(const float* __restrict__ centroid, const float* __restrict__ xyz,
             const float* __restrict__ radius,   const float* __restrict__ dist,
             const float* __restrict__ w_xyz,    const float* __restrict__ b_xyz)
{
    int t = threadIdx.x, lane = t & 31, w = t >> 5;
    int row = blockIdx.x * K1_WARPS + w;
    unsigned lmask = (1u << lane) - 1u;

    __shared__ int s_idx[K1_WARPS][KNN];

    float r = radius[row];
    const float* __restrict__ drow = dist + (size_t)row * NPTS;
    int cnt = 0;

    if (r >= 0.04f) {
        // fast path: 64-elem chunks, 1-deep prefetch; expected 1-10 iterations
        int base = 0;
        float d0 = drow[lane], d1 = drow[32 + lane];
        while (true) {
            int nb = base + 64;
            float n0 = 2.0f, n1 = 2.0f;
            if (nb < NPTS) { n0 = drow[nb + lane]; n1 = drow[nb + 32 + lane]; }
            unsigned m0 = __ballot_sync(0xffffffffu, d0 <= r);
            if (d0 <= r) {
                int pos = cnt + __popc(m0 & lmask);
                if (pos < KNN) s_idx[w][pos] = base + lane;
            }
            cnt += __popc(m0);
            unsigned m1 = __ballot_sync(0xffffffffu, d1 <= r);
            if (d1 <= r) {
                int pos = cnt + __popc(m1 & lmask);
                if (pos < KNN) s_idx[w][pos] = base + 32 + lane;
            }
            cnt += __popc(m1);
            if (cnt >= KNN || nb >= NPTS) break;
            base = nb; d0 = n0; d1 = n1;
        }
    } else {
        // slow path (rare): 256-elem chunks, 3-deep prefetch (MLP ~24)
        float buf[4][8];
#pragma unroll
        for (int q = 0; q < 4; q++)
#pragma unroll
            for (int s = 0; s < 8; s++) buf[q][s] = drow[q*256 + s*32 + lane];
        int base = 0;
#pragma unroll 1
        while (true) {
#pragma unroll
            for (int s = 0; s < 8; s++) {
                float d = buf[0][s];
                unsigned m = __ballot_sync(0xffffffffu, d <= r);
                if (d <= r) {
                    int pos = cnt + __popc(m & lmask);
                    if (pos < KNN) s_idx[w][pos] = base + s*32 + lane;
                }
                cnt += __popc(m);
            }
            if (cnt >= KNN || base + 256 >= NPTS) break;
            int nb = base + 1024;
#pragma unroll
            for (int q = 0; q < 3; q++)
#pragma unroll
                for (int s = 0; s < 8; s++) buf[q][s] = buf[q+1][s];
#pragma unroll
            for (int s = 0; s < 8; s++)
                buf[3][s] = (nb < NPTS) ? drow[nb + s*32 + lane] : 2.0f;
            base += 256;
        }
    }
    __syncwarp();

    // pad with first valid index (or N-1 clamp when none)
    if (lane < KNN) {
        int first = (cnt > 0) ? s_idx[w][0] : (NPTS - 1);
        int v = (lane < cnt) ? s_idx[w][lane] : first;
        s_idx[w][lane] = v;
    }
    __syncwarp();

    // BN0 stats + h min/max: lane = channel
    float a0=w_xyz[lane*9+0], a1=w_xyz[lane*9+1], a2=w_xyz[lane*9+2];
    float a3=w_xyz[lane*9+3], a4=w_xyz[lane*9+4], a5=w_xyz[lane*9+5];
    float a6=w_xyz[lane*9+6], a7=w_xyz[lane*9+7], a8=w_xyz[lane*9+8];
    float wc0=a0-a6, wc1=a1-a7, wc2=a2-a8;
    float wp0=a3+a6, wp1=a4+a7, wp2=a5+a8;
    float cx = centroid[row*3+0], cy = centroid[row*3+1], cz = centroid[row*3+2];
    const float* __restrict__ xb = xyz + (size_t)(row >> 11) * NPTS * 3;
    float hbase = b_xyz[lane] + wc0*cx + wc1*cy + wc2*cz;

    float ls = 0.0f, lss = 0.0f, hmin = 1e30f, hmax = -1e30f;
#pragma unroll
    for (int k = 0; k < KNN; k++) {
        int id = s_idx[w][k];           // warp-uniform -> broadcast
        float px = xb[id*3+0], py = xb[id*3+1], pz = xb[id*3+2];
        float h = hbase + wp0*px + wp1*py + wp2*pz;
        ls += h; lss += h*h;
        hmin = fminf(hmin, h); hmax = fmaxf(hmax, h);
    }
    g_hmm[row][0][lane] = hmin;
    g_hmm[row][1][lane] = hmax;
    int rep = row & (NB - 1);
    atomicAdd(&g_bins0[rep][lane],      ls);
    atomicAdd(&g_bins0[rep][C0 + lane], lss);
}

// ---------------- K2: BN0 hull + GELU + w1 -> h1, BN1 stats (no gather) ----------------
// GELU is unimodal => max_k gelu(bn(h_k)) = max(gelu at bn(hmin), bn(hmax)).
#define K2_RPW 4           // rows per warp
__global__ __launch_bounds__(256)
void k2(const float* __restrict__ g0, const float* __restrict__ be0,
        const float* __restrict__ w1)
{
    int t = threadIdx.x, lane = t & 31, w = t >> 5;
    __shared__ float s_sc0[C0], s_bi0[C0];
    __shared__ float s_w1[C1*33];
    __shared__ float s_sum[C1], s_ssq[C1];

    if (t < C0) {
        float s = 0.0f, ss = 0.0f;
        for (int rep = 0; rep < NB; rep++) { s += g_bins0[rep][t]; ss += g_bins0[rep][C0+t]; }
        float inv = 1.0f / (float)(NROWS * KNN);
        float mean = s * inv;
        float var  = ss * inv - mean * mean;
        float sc   = g0[t] * rsqrtf(var + EPSB);
        s_sc0[t] = sc; s_bi0[t] = be0[t] - mean * sc;
    }
    for (int i = t; i < C1*C0; i += 256) {
        int o = i >> 5, cc = i & 31;
        s_w1[o*33 + cc] = w1[i];
    }
    if (t < C1) { s_sum[t] = 0.0f; s_ssq[t] = 0.0f; }
    __syncthreads();

    float sc = s_sc0[lane], bi = s_bi0[lane];
    float sum0 = 0.0f, ssq0 = 0.0f, sum1 = 0.0f, ssq1 = 0.0f;

#pragma unroll
    for (int rr = 0; rr < K2_RPW; rr++) {
        int row = blockIdx.x * (8*K2_RPW) + w * K2_RPW + rr;
        float hmin = g_hmm[row][0][lane];
        float hmax = g_hmm[row][1][lane];
        float e0 = hmin * sc + bi;
        float e1 = hmax * sc + bi;
        float lo = fminf(e0, e1), hi = fmaxf(e0, e1);
        float m = fmaxf(gelu_exact(lo), gelu_exact(hi));

        float acc0 = 0.0f, acc1 = 0.0f;
#pragma unroll
        for (int cc = 0; cc < C0; cc++) {
            float xv = __shfl_sync(0xffffffffu, m, cc);
            acc0 += s_w1[lane*33 + cc] * xv;
            acc1 += s_w1[(lane+32)*33 + cc] * xv;
        }
        g_h1[(size_t)row*C1 + lane]      = acc0;
        g_h1[(size_t)row*C1 + lane + 32] = acc1;
        sum0 += acc0; ssq0 += acc0*acc0;
        sum1 += acc1; ssq1 += acc1*acc1;
    }

    atomicAdd(&s_sum[lane],      sum0);
    atomicAdd(&s_ssq[lane],      ssq0);
    atomicAdd(&s_sum[lane+32],   sum1);
    atomicAdd(&s_ssq[lane+32],   ssq1);
    __syncthreads();
    if (t < C1) {
        int rep = blockIdx.x & (NB - 1);
        atomicAdd(&g_bins1[rep][t],      s_sum[t]);
        atomicAdd(&g_bins1[rep][C1 + t], s_ssq[t]);
    }
}

// ---------------- K3: BN1+GELU fused + z = y @ w2^T, 8x4 tile, 512 thr, 1 wave ----------------
#define K3_R   64
#define K3_PAD (K3_R + 2)     // 66 floats/row: 8B-aligned row starts
__global__ __launch_bounds__(512)
void k3b(const float* __restrict__ g1, const float* __restrict__ be1)
{
    int t = threadIdx.x, lane = t & 31, w = t >> 5;
    int wc = w >> 3, wr = w & 7;            // channel-half (2), row-group (8)
    int row0 = blockIdx.x * K3_R;
    int o0 = wc * 128 + lane * 4;           // 4 consecutive output channels
    int r0 = wr * 8;                        // 8 rows

    __shared__ float s_sc[C1], s_bi[C1];
    __shared__ float s_yT[C1][K3_PAD];
    __shared__ float s_sum[C2], s_ssq[C2];

    if (t < C2) { s_sum[t] = 0.0f; s_ssq[t] = 0.0f; }
    if (t < C1) {
        float s = 0.0f, ss = 0.0f;
        for (int rep = 0; rep < NB; rep++) { s += g_bins1[rep][t]; ss += g_bins1[rep][C1+t]; }
        float inv = 1.0f / (float)NROWS;
        float mean = s * inv;
        float var  = ss * inv - mean * mean;
        float sc   = g1[t] * rsqrtf(var + EPSB);
        s_sc[t] = sc; s_bi[t] = be1[t] - mean * sc;
    }
    __syncthreads();

    // load h1 tile coalesced, BN1+GELU, store transposed [k][r]
#pragma unroll
    for (int i = 0; i < (K3_R*C1)/512; i++) {   // 8
        int j = t + i*512;
        int r = j >> 6, c = j & 63;
        float v = g_h1[(size_t)(row0 + r)*C1 + c];
        s_yT[c][r] = gelu_exact(v * s_sc[c] + s_bi[c]);
    }
    __syncthreads();

    unsigned long long acc[4][4];               // [channel j][row-pair p]
#pragma unroll
    for (int j = 0; j < 4; j++)
#pragma unroll
        for (int p = 0; p < 4; p++) acc[j][p] = 0ull;

    const float4* __restrict__ wt4 = reinterpret_cast<const float4*>(&g_w2T[0][0]);

#pragma unroll 16
    for (int k = 0; k < C1; k++) {
        const unsigned long long* yp =
            reinterpret_cast<const unsigned long long*>(&s_yT[k][r0]);
        unsigned long long y0 = yp[0], y1 = yp[1], y2 = yp[2], y3 = yp[3];
        float4 wv = wt4[k*(C2/4) + (o0 >> 2)];
        unsigned long long w0, w1, w2, w3;
        asm("mov.b64 %0, {%1, %1};" : "=l"(w0) : "f"(wv.x));
        asm("mov.b64 %0, {%1, %1};" : "=l"(w1) : "f"(wv.y));
        asm("mov.b64 %0, {%1, %1};" : "=l"(w2) : "f"(wv.z));
        asm("mov.b64 %0, {%1, %1};" : "=l"(w3) : "f"(wv.w));
        asm("fma.rn.f32x2 %0, %1, %2, %0;" : "+l"(acc[0][0]) : "l"(y0), "l"(w0));
        asm("fma.rn.f32x2 %0, %1, %2, %0;" : "+l"(acc[0][1]) : "l"(y1), "l"(w0));
        asm("fma.rn.f32x2 %0, %1, %2, %0;" : "+l"(acc[0][2]) : "l"(y2), "l"(w0));
        asm("fma.rn.f32x2 %0, %1, %2, %0;" : "+l"(acc[0][3]) : "l"(y3), "l"(w0));
        asm("fma.rn.f32x2 %0, %1, %2, %0;" : "+l"(acc[1][0]) : "l"(y0), "l"(w1));
        asm("fma.rn.f32x2 %0, %1, %2, %0;" : "+l"(acc[1][1]) : "l"(y1), "l"(w1));
        asm("fma.rn.f32x2 %0, %1, %2, %0;" : "+l"(acc[1][2]) : "l"(y2), "l"(w1));
        asm("fma.rn.f32x2 %0, %1, %2, %0;" : "+l"(acc[1][3]) : "l"(y3), "l"(w1));
        asm("fma.rn.f32x2 %0, %1, %2, %0;" : "+l"(acc[2][0]) : "l"(y0), "l"(w2));
        asm("fma.rn.f32x2 %0, %1, %2, %0;" : "+l"(acc[2][1]) : "l"(y1), "l"(w2));
        asm("fma.rn.f32x2 %0, %1, %2, %0;" : "+l"(acc[2][2]) : "l"(y2), "l"(w2));
        asm("fma.rn.f32x2 %0, %1, %2, %0;" : "+l"(acc[2][3]) : "l"(y3), "l"(w2));
        asm("fma.rn.f32x2 %0, %1, %2, %0;" : "+l"(acc[3][0]) : "l"(y0), "l"(w3));
        asm("fma.rn.f32x2 %0, %1, %2, %0;" : "+l"(acc[3][1]) : "l"(y1), "l"(w3));
        asm("fma.rn.f32x2 %0, %1, %2, %0;" : "+l"(acc[3][2]) : "l"(y2), "l"(w3));
        asm("fma.rn.f32x2 %0, %1, %2, %0;" : "+l"(acc[3][3]) : "l"(y3), "l"(w3));
    }

    // epilogue: store z (coalesced float4 per row) + per-channel partial stats
    float csum[4] = {0,0,0,0}, cssq[4] = {0,0,0,0};
#pragma unroll
    for (int p = 0; p < 4; p++) {
        float4 lo, hi;
        float zl[4], zh[4];
#pragma unroll
        for (int j = 0; j < 4; j++) {
            zl[j] = __uint_as_float((unsigned)(acc[j][p] & 0xffffffffull));
            zh[j] = __uint_as_float((unsigned)(acc[j][p] >> 32));
            csum[j] += zl[j] + zh[j];
            cssq[j] += zl[j]*zl[j] + zh[j]*zh[j];
        }
        lo.x=zl[0]; lo.y=zl[1]; lo.z=zl[2]; lo.w=zl[3];
        hi.x=zh[0]; hi.y=zh[1]; hi.z=zh[2]; hi.w=zh[3];
        int ra = row0 + r0 + 2*p;
        *reinterpret_cast<float4*>(&g_z[(size_t)ra*C2 + o0])     = lo;
        *reinterpret_cast<float4*>(&g_z[(size_t)(ra+1)*C2 + o0]) = hi;
    }
#pragma unroll
    for (int j = 0; j < 4; j++) {
        atomicAdd(&s_sum[o0 + j], csum[j]);
        atomicAdd(&s_ssq[o0 + j], cssq[j]);
    }
    __syncthreads();
    if (t < C2) {
        int rep = blockIdx.x & (NB - 1);
        atomicAdd(&g_bins2[rep][t],      s_sum[t]);
        atomicAdd(&g_bins2[rep][C2 + t], s_ssq[t]);
    }
}

// ---------------- K4: BN2 normalize -> out ----------------
__global__ __launch_bounds__(256)
void k4(const float* __restrict__ g2, const float* __restrict__ be2,
        float* __restrict__ out)
{
    int t = threadIdx.x;
    __shared__ float s_sc[C2], s_bi[C2];
    {
        float s = 0.0f, ss = 0.0f;
        for (int rep = 0; rep < NB; rep++) { s += g_bins2[rep][t]; ss += g_bins2[rep][C2+t]; }
        float inv = 1.0f / (float)NROWS;
        float mean = s * inv;
        float var  = ss * inv - mean * mean;
        float sc   = g2[t] * rsqrtf(var + EPSB);
        s_sc[t] = sc; s_bi[t] = be2[t] - mean * sc;
    }
    __syncthreads();
    const float4* __restrict__ z4 = reinterpret_cast<const float4*>(g_z);
    float4* __restrict__ o4 = reinterpret_cast<float4*>(out);
    const int total4 = NROWS * C2 / 4;
    for (int i = blockIdx.x * 256 + t; i < total4; i += gridDim.x * 256) {
        float4 v = z4[i];
        int c = (i & 63) * 4;
        v.x = v.x * s_sc[c+0] + s_bi[c+0];
        v.y = v.y * s_sc[c+1] + s_bi[c+1];
        v.z = v.z * s_sc[c+2] + s_bi[c+2];
        v.w = v.w * s_sc[c+3] + s_bi[c+3];
        o4[i] = v;
    }
}

// ---------------- launch ----------------
extern "C" void kernel_launch(void* const* d_in, const int* in_sizes, int n_in,
                              void* d_out, int out_size)
{
    const float* centroid = (const float*)d_in[0];
    const float* xyz      = (const float*)d_in[1];
    const float* radius   = (const float*)d_in[2];
    const float* dist     = (const float*)d_in[3];
    const float* w_xyz    = (const float*)d_in[4];
    const float* b_xyz    = (const float*)d_in[5];
    const float* g0       = (const float*)d_in[6];
    const float* be0      = (const float*)d_in[7];
    const float* w1       = (const float*)d_in[8];
    const float* g1       = (const float*)d_in[9];
    const float* be1      = (const float*)d_in[10];
    const float* w2       = (const float*)d_in[11];
    const float* g2       = (const float*)d_in[12];
    const float* be2      = (const float*)d_in[13];
    float* out = (float*)d_out;

    k_zero<<<128, 256>>>(w2);
    k1_scan<<<NROWS / K1_WARPS, 256>>>(centroid, xyz, radius, dist, w_xyz, b_xyz);
    k2<<<NROWS / (8*K2_RPW), 256>>>(g0, be0, w1);
    k3b<<<NROWS / K3_R, 512>>>(g1, be1);
    k4<<<512, 256>>>(g2, be2, out);
}